// round 11
// baseline (speedup 1.0000x reference)
#include <cuda_runtime.h>
#include <cuda_fp16.h>
#include <math.h>
#include <stdint.h>

// ---------------- problem constants ----------------
#define B_SZ   8192
#define XCOLS  145
#define IN_F   16
#define LAT    128
#define HID    1024
#define CS     6540     // (M+2)*K
#define CSP    6656     // CS padded to 256
#define MK     6528     // M*K
#define MK5    5440     // compacted (drop k%6==3, v==0); = 34*160
#define NGRP   1088     // MK5/5

// ---------------- scratch (zero-initialized device globals) -----------------
__device__ __half g_zhi [(size_t)B_SZ * LAT];
__device__ __half g_zlo [(size_t)B_SZ * LAT];
__device__ __half g_w1t [(size_t)HID * LAT];
__device__ __half g_h1h [(size_t)B_SZ * HID];
__device__ __half g_h2h [(size_t)B_SZ * CSP];     // pads stay zero
__device__ __half g_w2th[(size_t)CSP * HID];
__device__ __half g_w3th[(size_t)MK5 * CSP];      // compact, K-pads zero
__device__ float  g_w3t12[(size_t)12 * CSP];      // tail cols, pads zero
__device__ float  g_bias5[(size_t)MK5];           // expanded b3 per compact col
__device__ float  g_w   [(size_t)B_SZ * NGRP];    // fused weights
__device__ float  g_v5  [(size_t)B_SZ * 5];

// ---------------- low-level helpers ----------------
__device__ __forceinline__ uint32_t smem_u32(const void* p) {
    uint32_t a;
    asm("{ .reg .u64 t; cvta.to.shared.u64 t, %1; cvt.u32.u64 %0, t; }" : "=r"(a) : "l"(p));
    return a;
}
__device__ __forceinline__ void cpa16(uint32_t dst, const void* src) {
    asm volatile("cp.async.cg.shared.global [%0], [%1], 16;" :: "r"(dst), "l"(src));
}
#define CP_COMMIT() asm volatile("cp.async.commit_group;" ::: "memory")
#define CP_WAIT2()  asm volatile("cp.async.wait_group 2;" ::: "memory")
#define CP_WAIT0()  asm volatile("cp.async.wait_group 0;" ::: "memory")

__device__ __forceinline__ void ldsm4(uint32_t& r0, uint32_t& r1, uint32_t& r2, uint32_t& r3,
                                      uint32_t addr) {
    asm volatile("ldmatrix.sync.aligned.m8n8.x4.shared.b16 {%0,%1,%2,%3}, [%4];"
                 : "=r"(r0), "=r"(r1), "=r"(r2), "=r"(r3) : "r"(addr));
}
__device__ __forceinline__ void mma_f16(float* c, const uint32_t* a, uint32_t b0, uint32_t b1) {
    asm volatile(
        "mma.sync.aligned.m16n8k16.row.col.f32.f16.f16.f32 "
        "{%0,%1,%2,%3}, {%4,%5,%6,%7}, {%8,%9}, {%0,%1,%2,%3};"
        : "+f"(c[0]), "+f"(c[1]), "+f"(c[2]), "+f"(c[3])
        : "r"(a[0]), "r"(a[1]), "r"(a[2]), "r"(a[3]), "r"(b0), "r"(b1));
}
// fp16-accumulator variant: D (2 regs = 4 halves) += A·B
__device__ __forceinline__ void mma_h16(uint32_t* d, const uint32_t* a, uint32_t b0, uint32_t b1) {
    asm volatile(
        "mma.sync.aligned.m16n8k16.row.col.f16.f16.f16.f16 "
        "{%0,%1}, {%2,%3,%4,%5}, {%6,%7}, {%0,%1};"
        : "+r"(d[0]), "+r"(d[1])
        : "r"(a[0]), "r"(a[1]), "r"(a[2]), "r"(a[3]), "r"(b0), "r"(b1));
}

// ============================================================================
// GEMM (h1 / h2): fp16 HMMA f32-acc, tile 128x128, BK=64, 3 stages, 256 thr.
// TWOPASS: A = Ahi + Alo.  out fp16 = tanh(acc + bias[col])
// ============================================================================
#define ROWB1 144

template<int TWOPASS>
__global__ __launch_bounds__(256, TWOPASS ? 1 : 2)
void gemm_f16(const __half* __restrict__ A, const __half* __restrict__ Alo, int lda,
              const __half* __restrict__ B, int ldb, int nk,
              const float* __restrict__ bias,
              __half* __restrict__ outp, int ldo, int Nlimit)
{
    constexpr int ALO_OFF = 128 * ROWB1;
    constexpr int B_OFF   = (TWOPASS ? 256 : 128) * ROWB1;
    constexpr int STG     = (TWOPASS ? 384 : 256) * ROWB1;

    extern __shared__ char smem[];
    const uint32_t sbase = smem_u32(smem);
    const int tid  = threadIdx.x;
    const int lane = tid & 31;
    const int wid  = tid >> 5;
    const int warp_m = wid & 3;
    const int warp_n = wid >> 2;
    const int bm = blockIdx.y * 128;
    const int bn = blockIdx.x * 128;

    const int lrow = tid >> 1;
    const int lhalf = tid & 1;
    const char* aSrc  = (const char*)(A + (size_t)(bm + lrow) * lda) + lhalf * 64;
    const char* alSrc = (const char*)(Alo + (size_t)(bm + lrow) * lda) + lhalf * 64;
    const char* bSrc  = (const char*)(B + (size_t)(bn + lrow) * ldb) + lhalf * 64;
    const uint32_t dA = lrow * ROWB1 + lhalf * 64;

    float acc[2][8][4];
    #pragma unroll
    for (int i = 0; i < 2; ++i)
        #pragma unroll
        for (int j = 0; j < 8; ++j)
            #pragma unroll
            for (int l = 0; l < 4; ++l) acc[i][j][l] = 0.f;

    auto load_stage = [&](int s, int kc) {
        const uint32_t sA = sbase + s * STG;
        const size_t kb = (size_t)kc * 128;
        #pragma unroll
        for (int j = 0; j < 4; ++j) {
            cpa16(sA + dA + j * 16,         aSrc + kb + j * 16);
            if (TWOPASS) cpa16(sA + ALO_OFF + dA + j * 16, alSrc + kb + j * 16);
            cpa16(sA + B_OFF + dA + j * 16, bSrc + kb + j * 16);
        }
    };

    load_stage(0, 0); CP_COMMIT();
    if (nk > 1) load_stage(1, 1);
    CP_COMMIT();

    const int l15  = lane & 15;
    const int lksl = (lane >> 4) & 1;

    for (int k = 0; k < nk; ++k) {
        const int fetch = k + 2;
        if (fetch < nk) load_stage(fetch % 3, fetch);
        CP_COMMIT();
        CP_WAIT2();
        __syncthreads();

        const uint32_t sA = sbase + (k % 3) * STG;
        const uint32_t sB = sA + B_OFF;

        #pragma unroll
        for (int ks = 0; ks < 4; ++ks) {
            const uint32_t koff = ks * 32 + lksl * 16;
            uint32_t a[2][4], al[2][4];
            #pragma unroll
            for (int mt = 0; mt < 2; ++mt) {
                uint32_t ra = sA + (uint32_t)(warp_m * 32 + mt * 16 + l15) * ROWB1 + koff;
                ldsm4(a[mt][0], a[mt][1], a[mt][2], a[mt][3], ra);
                if (TWOPASS)
                    ldsm4(al[mt][0], al[mt][1], al[mt][2], al[mt][3], ra + ALO_OFF);
            }
            uint32_t bh[2][4];
            {
                uint32_t rb = sB + (uint32_t)(warp_n * 64 + l15) * ROWB1 + koff;
                ldsm4(bh[0][0], bh[0][1], bh[0][2], bh[0][3], rb);
            }
            #pragma unroll
            for (int g = 0; g < 4; ++g) {
                const int cur = g & 1, nxt = cur ^ 1;
                if (g < 3) {
                    uint32_t rb = sB + (uint32_t)(warp_n * 64 + (g + 1) * 16 + l15) * ROWB1 + koff;
                    ldsm4(bh[nxt][0], bh[nxt][1], bh[nxt][2], bh[nxt][3], rb);
                }
                float* c00 = acc[0][2 * g];
                float* c01 = acc[0][2 * g + 1];
                float* c10 = acc[1][2 * g];
                float* c11 = acc[1][2 * g + 1];
                mma_f16(c00, a[0], bh[cur][0], bh[cur][2]);
                mma_f16(c01, a[0], bh[cur][1], bh[cur][3]);
                mma_f16(c10, a[1], bh[cur][0], bh[cur][2]);
                mma_f16(c11, a[1], bh[cur][1], bh[cur][3]);
                if (TWOPASS) {
                    mma_f16(c00, al[0], bh[cur][0], bh[cur][2]);
                    mma_f16(c01, al[0], bh[cur][1], bh[cur][3]);
                    mma_f16(c10, al[1], bh[cur][0], bh[cur][2]);
                    mma_f16(c11, al[1], bh[cur][1], bh[cur][3]);
                }
            }
        }
        __syncthreads();
    }

    #pragma unroll
    for (int mt = 0; mt < 2; ++mt) {
        #pragma unroll
        for (int h = 0; h < 2; ++h) {
            const int row = bm + warp_m * 32 + mt * 16 + (lane >> 2) + h * 8;
            #pragma unroll
            for (int nt = 0; nt < 8; ++nt) {
                const int col = bn + warp_n * 64 + nt * 8 + ((lane & 3) << 1);
                if (col < Nlimit) {
                    float t0 = tanhf(acc[mt][nt][h * 2 + 0] + bias[col]);
                    float t1 = tanhf(acc[mt][nt][h * 2 + 1] + bias[col + 1]);
                    __half2 hp;
                    hp.x = __float2half(t0);
                    hp.y = __float2half(t1);
                    *reinterpret_cast<__half2*>(outp + (size_t)row * ldo + col) = hp;
                }
            }
        }
    }
}

// ============================================================================
// Big GEMM + fused group-of-5 reduction.
// Tile 128x160, BK=64, 3 stages, 256 thr.
// fp16 mma ACCUMULATORS per BK=64 chunk, flushed into fp32 master regs.
// w[b, m] = sum_{j5} (acc[b, m*5+j5] + bias5[m*5+j5]) * v5[b, j5]
// ============================================================================
#define W_BOFF (128 * ROWB1)            // 18432
#define W_STG  ((128 + 160) * ROWB1)    // 41472
#define W_SMEM (3 * W_STG)              // 124416
#define W_PADN 164

__global__ __launch_bounds__(256, 1)
void gemm_w(const __half* __restrict__ A, const __half* __restrict__ B,
            const float* __restrict__ bias5, const float* __restrict__ v5,
            float* __restrict__ w)
{
    extern __shared__ char smem[];
    const uint32_t sbase = smem_u32(smem);
    const int tid  = threadIdx.x;
    const int lane = tid & 31;
    const int wid  = tid >> 5;
    const int warp_m = wid & 3;           // 0..3 (32 rows each)
    const int warp_n = wid >> 2;          // 0..1 (80 cols each)
    const int bm = blockIdx.y * 128;
    const int bn = blockIdx.x * 160;

    float facc[2][10][4];
    #pragma unroll
    for (int i = 0; i < 2; ++i)
        #pragma unroll
        for (int j = 0; j < 10; ++j)
            #pragma unroll
            for (int l = 0; l < 4; ++l) facc[i][j][l] = 0.f;

    auto load_stage = [&](int s, int kc) {
        const uint32_t sb = sbase + s * W_STG;
        const char* ab = (const char*)A + ((size_t)bm * CSP + (size_t)kc * 64) * 2;
        const char* bb = (const char*)B + ((size_t)bn * CSP + (size_t)kc * 64) * 2;
        #pragma unroll
        for (int j = 0; j < 4; ++j) {           // A: 128 rows x 8 chunks
            int c = tid + j * 256;
            int r = c >> 3, q = c & 7;
            cpa16(sb + r * ROWB1 + q * 16, ab + (size_t)r * (CSP * 2) + q * 16);
        }
        #pragma unroll
        for (int j = 0; j < 5; ++j) {           // B: 160 rows x 8 chunks
            int c = tid + j * 256;
            int r = c >> 3, q = c & 7;
            cpa16(sb + W_BOFF + r * ROWB1 + q * 16, bb + (size_t)r * (CSP * 2) + q * 16);
        }
    };

    const int nk = CSP / 64;   // 104
    load_stage(0, 0); CP_COMMIT();
    load_stage(1, 1); CP_COMMIT();

    const int l15  = lane & 15;
    const int lksl = (lane >> 4) & 1;

    for (int k = 0; k < nk; ++k) {
        const int fetch = k + 2;
        if (fetch < nk) load_stage(fetch % 3, fetch);
        CP_COMMIT();
        CP_WAIT2();
        __syncthreads();

        const uint32_t sA = sbase + (k % 3) * W_STG;
        const uint32_t sB = sA + W_BOFF;

        // fp16 chunk accumulators (zeroed per BK=64 chunk)
        uint32_t hacc[2][10][2];
        #pragma unroll
        for (int i = 0; i < 2; ++i)
            #pragma unroll
            for (int j = 0; j < 10; ++j) { hacc[i][j][0] = 0u; hacc[i][j][1] = 0u; }

        #pragma unroll
        for (int ks = 0; ks < 4; ++ks) {
            const uint32_t koff = ks * 32 + lksl * 16;
            uint32_t a[2][4];
            #pragma unroll
            for (int mt = 0; mt < 2; ++mt) {
                uint32_t ra = sA + (uint32_t)(warp_m * 32 + mt * 16 + l15) * ROWB1 + koff;
                ldsm4(a[mt][0], a[mt][1], a[mt][2], a[mt][3], ra);
            }
            uint32_t bh[2][4];
            {
                uint32_t rb = sB + (uint32_t)(warp_n * 80 + l15) * ROWB1 + koff;
                ldsm4(bh[0][0], bh[0][1], bh[0][2], bh[0][3], rb);
            }
            #pragma unroll
            for (int g = 0; g < 5; ++g) {
                const int cur = g & 1, nxt = cur ^ 1;
                if (g < 4) {
                    uint32_t rb = sB + (uint32_t)(warp_n * 80 + (g + 1) * 16 + l15) * ROWB1 + koff;
                    ldsm4(bh[nxt][0], bh[nxt][1], bh[nxt][2], bh[nxt][3], rb);
                }
                mma_h16(hacc[0][2 * g],     a[0], bh[cur][0], bh[cur][2]);
                mma_h16(hacc[0][2 * g + 1], a[0], bh[cur][1], bh[cur][3]);
                mma_h16(hacc[1][2 * g],     a[1], bh[cur][0], bh[cur][2]);
                mma_h16(hacc[1][2 * g + 1], a[1], bh[cur][1], bh[cur][3]);
            }
        }

        // flush fp16 chunk accumulators into fp32 masters
        #pragma unroll
        for (int mt = 0; mt < 2; ++mt)
            #pragma unroll
            for (int nt = 0; nt < 10; ++nt) {
                float2 lo = __half22float2(*reinterpret_cast<__half2*>(&hacc[mt][nt][0]));
                float2 hi = __half22float2(*reinterpret_cast<__half2*>(&hacc[mt][nt][1]));
                facc[mt][nt][0] += lo.x;
                facc[mt][nt][1] += lo.y;
                facc[mt][nt][2] += hi.x;
                facc[mt][nt][3] += hi.y;
            }
        __syncthreads();
    }

    // ---------------- fused epilogue: stage tile, reduce groups of 5 --------
    CP_WAIT0();
    __syncthreads();

    float* stg = reinterpret_cast<float*>(smem);          // [128][164]
    float* v5s = stg + 128 * W_PADN;                       // [128][5]
    float* b5s = v5s + 128 * 5;                            // [160]

    #pragma unroll
    for (int mt = 0; mt < 2; ++mt) {
        #pragma unroll
        for (int h = 0; h < 2; ++h) {
            const int row = warp_m * 32 + mt * 16 + (lane >> 2) + h * 8;
            #pragma unroll
            for (int nt = 0; nt < 10; ++nt) {
                const int col = warp_n * 80 + nt * 8 + ((lane & 3) << 1);
                stg[row * W_PADN + col]     = facc[mt][nt][h * 2 + 0];
                stg[row * W_PADN + col + 1] = facc[mt][nt][h * 2 + 1];
            }
        }
    }
    for (int i = tid; i < 128 * 5; i += 256) v5s[i] = v5[(size_t)bm * 5 + i];
    if (tid < 160) b5s[tid] = bias5[bn + tid];
    __syncthreads();

    const int gbase = blockIdx.x * 32;
    for (int i = tid; i < 128 * 32; i += 256) {
        const int row = i >> 5, grp = i & 31;
        const float* p  = stg + row * W_PADN + grp * 5;
        const float* vv = v5s + row * 5;
        const float* bb = b5s + grp * 5;
        float s = (p[0] + bb[0]) * vv[0];
        s = fmaf(p[1] + bb[1], vv[1], s);
        s = fmaf(p[2] + bb[2], vv[2], s);
        s = fmaf(p[3] + bb[3], vv[3], s);
        s = fmaf(p[4] + bb[4], vv[4], s);
        w[(size_t)(bm + row) * NGRP + gbase + grp] = s;
    }
}

// ---------------- transpose + fp16 (optionally compact k%6==3) --------------
__global__ __launch_bounds__(256)
void transpose_h(const float* __restrict__ W, int R, int Cstride, int nlimit,
                 __half* __restrict__ Thi, int ldt, int compact)
{
    __shared__ float ts[32][33];
    const int tx = threadIdx.x, ty = threadIdx.y;
    const int n0 = blockIdx.x * 32, k0 = blockIdx.y * 32;
    #pragma unroll
    for (int i = 0; i < 32; i += 8) {
        int k = k0 + ty + i, n = n0 + tx;
        ts[ty + i][tx] = (k < R && n < nlimit) ? W[(size_t)k * Cstride + n] : 0.f;
    }
    __syncthreads();
    #pragma unroll
    for (int i = 0; i < 32; i += 8) {
        int n = n0 + ty + i, k = k0 + tx;
        if (n < nlimit && k < R) {
            int np = n;
            if (compact) {
                int r6 = n % 6;
                if (r6 == 3) continue;
                np = (n / 6) * 5 + (r6 < 3 ? r6 : r6 - 1);
            }
            Thi[(size_t)np * ldt + k] = __float2half(ts[tx][ty + i]);
        }
    }
}

// ---------------- gather W3 tail cols + bias5 --------------------------------
__global__ __launch_bounds__(256)
void gather_tail(const float* __restrict__ W3, const float* __restrict__ b3,
                 float* __restrict__ w3t12, float* __restrict__ bias5)
{
    int i = blockIdx.x * 256 + threadIdx.x;
    if (i < CS * 12) {
        int c = i / 12, j = i % 12;
        w3t12[(size_t)j * CSP + c] = W3[(size_t)c * CS + MK + j];
    }
    if (i < MK5) {
        int m6 = i / 5, j5 = i - m6 * 5;
        int kk = (j5 < 3) ? j5 : j5 + 1;
        bias5[i] = b3[m6 * 6 + kk];
    }
}

// ---------------- z -> fp16 hi/lo (contiguous [B][128]) ---------------------
__global__ __launch_bounds__(256)
void zprep(const float* __restrict__ x, __half* __restrict__ zhi, __half* __restrict__ zlo)
{
    int i = blockIdx.x * 256 + threadIdx.x;
    if (i < B_SZ * LAT) {
        int b = i >> 7, c = i & 127;
        float v = x[(size_t)b * XCOLS + (IN_F + 1) + c];
        __half h = __float2half(v);
        zhi[i] = h;
        zlo[i] = __float2half(v - __half2float(h));
    }
}

// ---------------- tail GEMM: 32 rows/block, 8 thr/row, shfl reduce ----------
__global__ __launch_bounds__(256)
void tail_gemm(const __half* __restrict__ h2h,
               const float* __restrict__ w3t12,
               const float* __restrict__ b3,
               const float* __restrict__ x,
               float* __restrict__ v5)
{
    __shared__ __half h2s[32 * 72];
    __shared__ float  w3s[64 * 12];

    const int tid = threadIdx.x;
    const int bm = blockIdx.x * 32;
    const int row_l = tid >> 3;       // 0..31
    const int ksub = tid & 7;

    float acc[12];
    #pragma unroll
    for (int j = 0; j < 12; ++j) acc[j] = 0.f;

    for (int kc = 0; kc < CSP / 64; ++kc) {
        {
            uint4 v = *reinterpret_cast<const uint4*>(
                h2h + (size_t)(bm + row_l) * CSP + kc * 64 + ksub * 8);
            *reinterpret_cast<uint4*>(&h2s[row_l * 72 + ksub * 8]) = v;
        }
        for (int i = tid; i < 64 * 12; i += 256) {
            int k = i / 12, j = i % 12;
            w3s[i] = w3t12[(size_t)j * CSP + kc * 64 + k];
        }
        __syncthreads();

        #pragma unroll
        for (int kk = 0; kk < 8; ++kk) {
            int k = kk * 8 + ksub;
            float hv = __half2float(h2s[row_l * 72 + k]);
            #pragma unroll
            for (int j = 0; j < 12; ++j)
                acc[j] = fmaf(hv, w3s[k * 12 + j], acc[j]);
        }
        __syncthreads();
    }

    #pragma unroll
    for (int j = 0; j < 12; ++j) {
        #pragma unroll
        for (int d = 4; d > 0; d >>= 1)
            acc[j] += __shfl_down_sync(0xffffffffu, acc[j], d);
    }

    if (ksub == 0) {
        float s = x[(size_t)(B_SZ - 1) * XCOLS + IN_F];
        float dt[12];
        #pragma unroll
        for (int j = 0; j < 12; ++j) dt[j] = acc[j] + b3[MK + j];
        #pragma unroll
        for (int t5 = 0; t5 < 5; ++t5) {
            int k = (t5 < 3) ? t5 : t5 + 1;
            float sv = fmaf(s, dt[k], dt[k + 6]);
            float r = (k < 3) ? cosf(sv * (float)k) : sinf(sv * (float)(k - 3));
            v5[(size_t)(bm + row_l) * 5 + t5] = r;
        }
    }
}

// ---------------- final: out[b,o] = sum_i inp[b,i]*w[b,i*64+o] + w[b,1024+o] -
__global__ __launch_bounds__(256)
void final_kernel(const float* __restrict__ w,
                  const float* __restrict__ x,
                  float* __restrict__ out)
{
    __shared__ float inp[4][IN_F];
    const int tid = threadIdx.x;
    const int b0 = blockIdx.x * 4;
    if (tid < 4 * IN_F)
        inp[tid >> 4][tid & 15] = x[(size_t)(b0 + (tid >> 4)) * XCOLS + (tid & 15)];
    __syncthreads();

    const int r = tid >> 6;
    const int o = tid & 63;
    const int b = b0 + r;
    const float* wr = w + (size_t)b * NGRP;
    float accum = wr[1024 + o];
    #pragma unroll
    for (int i = 0; i < IN_F; ++i)
        accum = fmaf(inp[r][i], wr[i * 64 + o], accum);
    out[(size_t)b * 64 + o] = accum;
}

// ----------------------------- launch ---------------------------------------
extern "C" void kernel_launch(void* const* d_in, const int* in_sizes, int n_in,
                              void* d_out, int out_size)
{
    const float* x  = (const float*)d_in[0];
    const float* W1 = (const float*)d_in[1];
    const float* b1 = (const float*)d_in[2];
    const float* W2 = (const float*)d_in[3];
    const float* b2 = (const float*)d_in[4];
    const float* W3 = (const float*)d_in[5];
    const float* b3 = (const float*)d_in[6];
    float* out = (float*)d_out;

    __half *zhi, *zlo, *w1t, *h1h, *h2h, *w2th, *w3th;
    float *w3t12, *bias5, *wbuf, *v5;
    cudaGetSymbolAddress((void**)&zhi,  g_zhi);
    cudaGetSymbolAddress((void**)&zlo,  g_zlo);
    cudaGetSymbolAddress((void**)&w1t,  g_w1t);
    cudaGetSymbolAddress((void**)&h1h,  g_h1h);
    cudaGetSymbolAddress((void**)&h2h,  g_h2h);
    cudaGetSymbolAddress((void**)&w2th, g_w2th);
    cudaGetSymbolAddress((void**)&w3th, g_w3th);
    cudaGetSymbolAddress((void**)&w3t12, g_w3t12);
    cudaGetSymbolAddress((void**)&bias5, g_bias5);
    cudaGetSymbolAddress((void**)&wbuf, g_w);
    cudaGetSymbolAddress((void**)&v5,  g_v5);

    const int SM_2P = 3 * 384 * ROWB1;   // 165888
    const int SM_1P = 3 * 256 * ROWB1;   // 110592

    static bool attr_set = false;
    if (!attr_set) {
        cudaFuncSetAttribute(gemm_f16<1>, cudaFuncAttributeMaxDynamicSharedMemorySize, SM_2P);
        cudaFuncSetAttribute(gemm_f16<0>, cudaFuncAttributeMaxDynamicSharedMemorySize, SM_1P);
        cudaFuncSetAttribute(gemm_w, cudaFuncAttributeMaxDynamicSharedMemorySize, W_SMEM);
        attr_set = true;
    }

    // 0) prep
    transpose_h<<<dim3((CS + 31) / 32, (HID + 31) / 32), dim3(32, 8)>>>(
        W2, HID, CS, CS, w2th, HID, 0);
    transpose_h<<<dim3((MK + 31) / 32, (CS + 31) / 32), dim3(32, 8)>>>(
        W3, CS, CS, MK, w3th, CSP, 1);
    transpose_h<<<dim3((HID + 31) / 32, (LAT + 31) / 32), dim3(32, 8)>>>(
        W1, LAT, HID, HID, w1t, LAT, 0);
    gather_tail<<<(CS * 12 + 255) / 256, 256>>>(W3, b3, w3t12, bias5);
    zprep<<<(B_SZ * LAT + 255) / 256, 256>>>(x, zhi, zlo);

    // 1) h1 = tanh(z @ W1 + b1): 2-pass (exact z), K=128
    gemm_f16<1><<<dim3(HID / 128, B_SZ / 128), 256, SM_2P>>>(
        zhi, zlo, LAT, w1t, LAT, LAT / 64, b1, h1h, HID, HID);

    // 2) h2 = tanh(h1 @ W2 + b2): 1-pass, K=1024
    gemm_f16<0><<<dim3(CSP / 128, B_SZ / 128), 256, SM_1P>>>(
        h1h, nullptr, HID, w2th, HID, HID / 64, b2, h2h, CSP, CS);

    // 3) tail mini-GEMM -> v5 (256 blocks)
    tail_gemm<<<B_SZ / 32, 256>>>(h2h, w3t12, b3, x, v5);

    // 4) big GEMM (fp16-acc chunks) + fused group-of-5 reduction -> w[B][1088]
    gemm_w<<<dim3(MK5 / 160, B_SZ / 128), 256, W_SMEM>>>(
        h2h, w3th, bias5, v5, wbuf);

    // 5) adaptive 16->64 linear from fused weights
    final_kernel<<<B_SZ / 4, 256>>>(wbuf, x, out);
}

// round 12
// speedup vs baseline: 1.1108x; 1.1108x over previous
#include <cuda_runtime.h>
#include <cuda_fp16.h>
#include <math.h>
#include <stdint.h>

// ---------------- problem constants ----------------
#define B_SZ   8192
#define XCOLS  145
#define IN_F   16
#define LAT    128
#define HID    1024
#define CS     6540     // (M+2)*K
#define CSP    6656     // CS padded to 256
#define MK     6528     // M*K
#define MK5    5440     // compacted (drop k%6==3, v==0); = 34*160
#define NGRP   1088     // MK5/5

// ---------------- scratch (zero-initialized device globals) -----------------
__device__ __half g_zhi [(size_t)B_SZ * LAT];
__device__ __half g_zlo [(size_t)B_SZ * LAT];
__device__ __half g_w1t [(size_t)HID * LAT];
__device__ __half g_h1h [(size_t)B_SZ * HID];
__device__ __half g_h2h [(size_t)B_SZ * CSP];     // pads stay zero
__device__ __half g_w2th[(size_t)CSP * HID];
__device__ __half g_w3th[(size_t)MK5 * CSP];      // compact, K-pads zero
__device__ float  g_w3t12[(size_t)12 * CSP];      // tail cols, pads zero
__device__ float  g_bias5[(size_t)MK5];           // expanded b3 per compact col
__device__ float  g_w   [(size_t)B_SZ * NGRP];    // fused weights
__device__ float  g_v5  [(size_t)B_SZ * 5];

// ---------------- low-level helpers ----------------
__device__ __forceinline__ uint32_t smem_u32(const void* p) {
    uint32_t a;
    asm("{ .reg .u64 t; cvta.to.shared.u64 t, %1; cvt.u32.u64 %0, t; }" : "=r"(a) : "l"(p));
    return a;
}
__device__ __forceinline__ void cpa16(uint32_t dst, const void* src) {
    asm volatile("cp.async.cg.shared.global [%0], [%1], 16;" :: "r"(dst), "l"(src));
}
#define CP_COMMIT() asm volatile("cp.async.commit_group;" ::: "memory")
#define CP_WAIT2()  asm volatile("cp.async.wait_group 2;" ::: "memory")
#define CP_WAIT0()  asm volatile("cp.async.wait_group 0;" ::: "memory")

__device__ __forceinline__ void ldsm4(uint32_t& r0, uint32_t& r1, uint32_t& r2, uint32_t& r3,
                                      uint32_t addr) {
    asm volatile("ldmatrix.sync.aligned.m8n8.x4.shared.b16 {%0,%1,%2,%3}, [%4];"
                 : "=r"(r0), "=r"(r1), "=r"(r2), "=r"(r3) : "r"(addr));
}
__device__ __forceinline__ void mma_f16(float* c, const uint32_t* a, uint32_t b0, uint32_t b1) {
    asm volatile(
        "mma.sync.aligned.m16n8k16.row.col.f32.f16.f16.f32 "
        "{%0,%1,%2,%3}, {%4,%5,%6,%7}, {%8,%9}, {%0,%1,%2,%3};"
        : "+f"(c[0]), "+f"(c[1]), "+f"(c[2]), "+f"(c[3])
        : "r"(a[0]), "r"(a[1]), "r"(a[2]), "r"(a[3]), "r"(b0), "r"(b1));
}

// ============================================================================
// GEMM (h1 / h2): fp16 HMMA f32-acc, tile 128x128, BK=64, 3 stages, 256 thr.
// TWOPASS: A = Ahi + Alo.  out fp16 = tanh(acc + bias[col])
// ============================================================================
#define ROWB1 144

template<int TWOPASS>
__global__ __launch_bounds__(256, TWOPASS ? 1 : 2)
void gemm_f16(const __half* __restrict__ A, const __half* __restrict__ Alo, int lda,
              const __half* __restrict__ B, int ldb, int nk,
              const float* __restrict__ bias,
              __half* __restrict__ outp, int ldo, int Nlimit)
{
    constexpr int ALO_OFF = 128 * ROWB1;
    constexpr int B_OFF   = (TWOPASS ? 256 : 128) * ROWB1;
    constexpr int STG     = (TWOPASS ? 384 : 256) * ROWB1;

    extern __shared__ char smem[];
    const uint32_t sbase = smem_u32(smem);
    const int tid  = threadIdx.x;
    const int lane = tid & 31;
    const int wid  = tid >> 5;
    const int warp_m = wid & 3;
    const int warp_n = wid >> 2;
    const int bm = blockIdx.y * 128;
    const int bn = blockIdx.x * 128;

    const int lrow = tid >> 1;
    const int lhalf = tid & 1;
    const char* aSrc  = (const char*)(A + (size_t)(bm + lrow) * lda) + lhalf * 64;
    const char* alSrc = (const char*)(Alo + (size_t)(bm + lrow) * lda) + lhalf * 64;
    const char* bSrc  = (const char*)(B + (size_t)(bn + lrow) * ldb) + lhalf * 64;
    const uint32_t dA = lrow * ROWB1 + lhalf * 64;

    float acc[2][8][4];
    #pragma unroll
    for (int i = 0; i < 2; ++i)
        #pragma unroll
        for (int j = 0; j < 8; ++j)
            #pragma unroll
            for (int l = 0; l < 4; ++l) acc[i][j][l] = 0.f;

    auto load_stage = [&](int s, int kc) {
        const uint32_t sA = sbase + s * STG;
        const size_t kb = (size_t)kc * 128;
        #pragma unroll
        for (int j = 0; j < 4; ++j) {
            cpa16(sA + dA + j * 16,         aSrc + kb + j * 16);
            if (TWOPASS) cpa16(sA + ALO_OFF + dA + j * 16, alSrc + kb + j * 16);
            cpa16(sA + B_OFF + dA + j * 16, bSrc + kb + j * 16);
        }
    };

    load_stage(0, 0); CP_COMMIT();
    if (nk > 1) load_stage(1, 1);
    CP_COMMIT();

    const int l15  = lane & 15;
    const int lksl = (lane >> 4) & 1;

    for (int k = 0; k < nk; ++k) {
        const int fetch = k + 2;
        if (fetch < nk) load_stage(fetch % 3, fetch);
        CP_COMMIT();
        CP_WAIT2();
        __syncthreads();

        const uint32_t sA = sbase + (k % 3) * STG;
        const uint32_t sB = sA + B_OFF;

        #pragma unroll
        for (int ks = 0; ks < 4; ++ks) {
            const uint32_t koff = ks * 32 + lksl * 16;
            uint32_t a[2][4], al[2][4];
            #pragma unroll
            for (int mt = 0; mt < 2; ++mt) {
                uint32_t ra = sA + (uint32_t)(warp_m * 32 + mt * 16 + l15) * ROWB1 + koff;
                ldsm4(a[mt][0], a[mt][1], a[mt][2], a[mt][3], ra);
                if (TWOPASS)
                    ldsm4(al[mt][0], al[mt][1], al[mt][2], al[mt][3], ra + ALO_OFF);
            }
            uint32_t bh[2][4];
            {
                uint32_t rb = sB + (uint32_t)(warp_n * 64 + l15) * ROWB1 + koff;
                ldsm4(bh[0][0], bh[0][1], bh[0][2], bh[0][3], rb);
            }
            #pragma unroll
            for (int g = 0; g < 4; ++g) {
                const int cur = g & 1, nxt = cur ^ 1;
                if (g < 3) {
                    uint32_t rb = sB + (uint32_t)(warp_n * 64 + (g + 1) * 16 + l15) * ROWB1 + koff;
                    ldsm4(bh[nxt][0], bh[nxt][1], bh[nxt][2], bh[nxt][3], rb);
                }
                float* c00 = acc[0][2 * g];
                float* c01 = acc[0][2 * g + 1];
                float* c10 = acc[1][2 * g];
                float* c11 = acc[1][2 * g + 1];
                mma_f16(c00, a[0], bh[cur][0], bh[cur][2]);
                mma_f16(c01, a[0], bh[cur][1], bh[cur][3]);
                mma_f16(c10, a[1], bh[cur][0], bh[cur][2]);
                mma_f16(c11, a[1], bh[cur][1], bh[cur][3]);
                if (TWOPASS) {
                    mma_f16(c00, al[0], bh[cur][0], bh[cur][2]);
                    mma_f16(c01, al[0], bh[cur][1], bh[cur][3]);
                    mma_f16(c10, al[1], bh[cur][0], bh[cur][2]);
                    mma_f16(c11, al[1], bh[cur][1], bh[cur][3]);
                }
            }
        }
        __syncthreads();
    }

    #pragma unroll
    for (int mt = 0; mt < 2; ++mt) {
        #pragma unroll
        for (int h = 0; h < 2; ++h) {
            const int row = bm + warp_m * 32 + mt * 16 + (lane >> 2) + h * 8;
            #pragma unroll
            for (int nt = 0; nt < 8; ++nt) {
                const int col = bn + warp_n * 64 + nt * 8 + ((lane & 3) << 1);
                if (col < Nlimit) {
                    float t0 = tanhf(acc[mt][nt][h * 2 + 0] + bias[col]);
                    float t1 = tanhf(acc[mt][nt][h * 2 + 1] + bias[col + 1]);
                    __half2 hp;
                    hp.x = __float2half(t0);
                    hp.y = __float2half(t1);
                    *reinterpret_cast<__half2*>(outp + (size_t)row * ldo + col) = hp;
                }
            }
        }
    }
}

// ============================================================================
// Big GEMM + fused group-of-5 reduction: tile 256x160, BK=64, 3 stages, 512thr.
// (round-10 winner, reverted from the fp16-acc experiment)
// w[b, m] = sum_{j5} (acc[b, m*5+j5] + bias5[m*5+j5]) * v5[b, j5]
// ============================================================================
#define W_BOFF (256 * ROWB1)            // 36864
#define W_STG  ((256 + 160) * ROWB1)    // 59904
#define W_SMEM (3 * W_STG)              // 179712
#define W_PADN 164

__global__ __launch_bounds__(512, 1)
void gemm_w(const __half* __restrict__ A, const __half* __restrict__ B,
            const float* __restrict__ bias5, const float* __restrict__ v5,
            float* __restrict__ w)
{
    extern __shared__ char smem[];
    const uint32_t sbase = smem_u32(smem);
    const int tid  = threadIdx.x;
    const int lane = tid & 31;
    const int wid  = tid >> 5;
    const int warp_m = wid & 7;           // 0..7 (32 rows each)
    const int warp_n = wid >> 3;          // 0..1 (80 cols each)
    const int bm = blockIdx.y * 256;
    const int bn = blockIdx.x * 160;

    const bool isA = tid < 256;
    const int ltid = isA ? tid : tid - 256;
    const int lrow = ltid >> 3;
    const int lcol = ltid & 7;
    const char* gsrc = isA
        ? (const char*)(A + (size_t)(bm + lrow) * CSP) + lcol * 16
        : (const char*)(B + (size_t)(bn + lrow) * CSP) + lcol * 16;
    const uint32_t dst0 = (isA ? 0u : (uint32_t)W_BOFF) + lrow * ROWB1 + lcol * 16;
    const size_t gstr = (size_t)32 * CSP * 2;

    float acc[2][10][4];
    #pragma unroll
    for (int i = 0; i < 2; ++i)
        #pragma unroll
        for (int j = 0; j < 10; ++j)
            #pragma unroll
            for (int l = 0; l < 4; ++l) acc[i][j][l] = 0.f;

    auto load_stage = [&](int s, int kc) {
        const uint32_t base = sbase + s * W_STG + dst0;
        const char* g = gsrc + (size_t)kc * 128;
        if (isA) {
            #pragma unroll
            for (int t = 0; t < 8; ++t)
                cpa16(base + t * (32 * ROWB1), g + t * gstr);
        } else {
            #pragma unroll
            for (int t = 0; t < 5; ++t)
                cpa16(base + t * (32 * ROWB1), g + t * gstr);
        }
    };

    const int nk = CSP / 64;   // 104
    load_stage(0, 0); CP_COMMIT();
    load_stage(1, 1); CP_COMMIT();

    const int l15  = lane & 15;
    const int lksl = (lane >> 4) & 1;

    for (int k = 0; k < nk; ++k) {
        const int fetch = k + 2;
        if (fetch < nk) load_stage(fetch % 3, fetch);
        CP_COMMIT();
        CP_WAIT2();
        __syncthreads();

        const uint32_t sA = sbase + (k % 3) * W_STG;
        const uint32_t sB = sA + W_BOFF;

        #pragma unroll
        for (int ks = 0; ks < 4; ++ks) {
            const uint32_t koff = ks * 32 + lksl * 16;
            uint32_t a[2][4];
            #pragma unroll
            for (int mt = 0; mt < 2; ++mt) {
                uint32_t ra = sA + (uint32_t)(warp_m * 32 + mt * 16 + l15) * ROWB1 + koff;
                ldsm4(a[mt][0], a[mt][1], a[mt][2], a[mt][3], ra);
            }
            uint32_t bh[2][4];
            {
                uint32_t rb = sB + (uint32_t)(warp_n * 80 + l15) * ROWB1 + koff;
                ldsm4(bh[0][0], bh[0][1], bh[0][2], bh[0][3], rb);
            }
            #pragma unroll
            for (int g = 0; g < 5; ++g) {
                const int cur = g & 1, nxt = cur ^ 1;
                if (g < 4) {
                    uint32_t rb = sB + (uint32_t)(warp_n * 80 + (g + 1) * 16 + l15) * ROWB1 + koff;
                    ldsm4(bh[nxt][0], bh[nxt][1], bh[nxt][2], bh[nxt][3], rb);
                }
                mma_f16(acc[0][2 * g],     a[0], bh[cur][0], bh[cur][2]);
                mma_f16(acc[0][2 * g + 1], a[0], bh[cur][1], bh[cur][3]);
                mma_f16(acc[1][2 * g],     a[1], bh[cur][0], bh[cur][2]);
                mma_f16(acc[1][2 * g + 1], a[1], bh[cur][1], bh[cur][3]);
            }
        }
        __syncthreads();
    }

    // ---------------- fused epilogue: stage tile, reduce groups of 5 --------
    CP_WAIT0();
    __syncthreads();

    float* stg = reinterpret_cast<float*>(smem);          // [256][164]
    float* v5s = stg + 256 * W_PADN;                       // [256][5]
    float* b5s = v5s + 256 * 5;                            // [160]

    #pragma unroll
    for (int mt = 0; mt < 2; ++mt) {
        #pragma unroll
        for (int h = 0; h < 2; ++h) {
            const int row = warp_m * 32 + mt * 16 + (lane >> 2) + h * 8;
            #pragma unroll
            for (int nt = 0; nt < 10; ++nt) {
                const int col = warp_n * 80 + nt * 8 + ((lane & 3) << 1);
                stg[row * W_PADN + col]     = acc[mt][nt][h * 2 + 0];
                stg[row * W_PADN + col + 1] = acc[mt][nt][h * 2 + 1];
            }
        }
    }
    for (int i = tid; i < 256 * 5; i += 512) v5s[i] = v5[(size_t)bm * 5 + i];
    if (tid < 160) b5s[tid] = bias5[bn + tid];
    __syncthreads();

    const int gbase = blockIdx.x * 32;
    for (int i = tid; i < 256 * 32; i += 512) {
        const int row = i >> 5, grp = i & 31;
        const float* p  = stg + row * W_PADN + grp * 5;
        const float* vv = v5s + row * 5;
        const float* bb = b5s + grp * 5;
        float s = (p[0] + bb[0]) * vv[0];
        s = fmaf(p[1] + bb[1], vv[1], s);
        s = fmaf(p[2] + bb[2], vv[2], s);
        s = fmaf(p[3] + bb[3], vv[3], s);
        s = fmaf(p[4] + bb[4], vv[4], s);
        w[(size_t)(bm + row) * NGRP + gbase + grp] = s;
    }
}

// ---------------- transpose + fp16 (optionally compact k%6==3) --------------
__global__ __launch_bounds__(256)
void transpose_h(const float* __restrict__ W, int R, int Cstride, int nlimit,
                 __half* __restrict__ Thi, int ldt, int compact)
{
    __shared__ float ts[32][33];
    const int tx = threadIdx.x, ty = threadIdx.y;
    const int n0 = blockIdx.x * 32, k0 = blockIdx.y * 32;
    #pragma unroll
    for (int i = 0; i < 32; i += 8) {
        int k = k0 + ty + i, n = n0 + tx;
        ts[ty + i][tx] = (k < R && n < nlimit) ? W[(size_t)k * Cstride + n] : 0.f;
    }
    __syncthreads();
    #pragma unroll
    for (int i = 0; i < 32; i += 8) {
        int n = n0 + ty + i, k = k0 + tx;
        if (n < nlimit && k < R) {
            int np = n;
            if (compact) {
                int r6 = n % 6;
                if (r6 == 3) continue;
                np = (n / 6) * 5 + (r6 < 3 ? r6 : r6 - 1);
            }
            Thi[(size_t)np * ldt + k] = __float2half(ts[tx][ty + i]);
        }
    }
}

// ---------------- gather W3 tail cols + bias5 --------------------------------
__global__ __launch_bounds__(256)
void gather_tail(const float* __restrict__ W3, const float* __restrict__ b3,
                 float* __restrict__ w3t12, float* __restrict__ bias5)
{
    int i = blockIdx.x * 256 + threadIdx.x;
    if (i < CS * 12) {
        int c = i / 12, j = i % 12;
        w3t12[(size_t)j * CSP + c] = W3[(size_t)c * CS + MK + j];
    }
    if (i < MK5) {
        int m6 = i / 5, j5 = i - m6 * 5;
        int kk = (j5 < 3) ? j5 : j5 + 1;
        bias5[i] = b3[m6 * 6 + kk];
    }
}

// ---------------- z -> fp16 hi/lo (contiguous [B][128]) ---------------------
__global__ __launch_bounds__(256)
void zprep(const float* __restrict__ x, __half* __restrict__ zhi, __half* __restrict__ zlo)
{
    int i = blockIdx.x * 256 + threadIdx.x;
    if (i < B_SZ * LAT) {
        int b = i >> 7, c = i & 127;
        float v = x[(size_t)b * XCOLS + (IN_F + 1) + c];
        __half h = __float2half(v);
        zhi[i] = h;
        zlo[i] = __float2half(v - __half2float(h));
    }
}

// ---------------- tail GEMM: 32 rows/block, 8 thr/row, shfl reduce ----------
__global__ __launch_bounds__(256)
void tail_gemm(const __half* __restrict__ h2h,
               const float* __restrict__ w3t12,
               const float* __restrict__ b3,
               const float* __restrict__ x,
               float* __restrict__ v5)
{
    __shared__ __half h2s[32 * 72];
    __shared__ float  w3s[64 * 12];

    const int tid = threadIdx.x;
    const int bm = blockIdx.x * 32;
    const int row_l = tid >> 3;
    const int ksub = tid & 7;

    float acc[12];
    #pragma unroll
    for (int j = 0; j < 12; ++j) acc[j] = 0.f;

    for (int kc = 0; kc < CSP / 64; ++kc) {
        {
            uint4 v = *reinterpret_cast<const uint4*>(
                h2h + (size_t)(bm + row_l) * CSP + kc * 64 + ksub * 8);
            *reinterpret_cast<uint4*>(&h2s[row_l * 72 + ksub * 8]) = v;
        }
        for (int i = tid; i < 64 * 12; i += 256) {
            int k = i / 12, j = i % 12;
            w3s[i] = w3t12[(size_t)j * CSP + kc * 64 + k];
        }
        __syncthreads();

        #pragma unroll
        for (int kk = 0; kk < 8; ++kk) {
            int k = kk * 8 + ksub;
            float hv = __half2float(h2s[row_l * 72 + k]);
            #pragma unroll
            for (int j = 0; j < 12; ++j)
                acc[j] = fmaf(hv, w3s[k * 12 + j], acc[j]);
        }
        __syncthreads();
    }

    #pragma unroll
    for (int j = 0; j < 12; ++j) {
        #pragma unroll
        for (int d = 4; d > 0; d >>= 1)
            acc[j] += __shfl_down_sync(0xffffffffu, acc[j], d);
    }

    if (ksub == 0) {
        float s = x[(size_t)(B_SZ - 1) * XCOLS + IN_F];
        float dt[12];
        #pragma unroll
        for (int j = 0; j < 12; ++j) dt[j] = acc[j] + b3[MK + j];
        #pragma unroll
        for (int t5 = 0; t5 < 5; ++t5) {
            int k = (t5 < 3) ? t5 : t5 + 1;
            float sv = fmaf(s, dt[k], dt[k + 6]);
            float r = (k < 3) ? cosf(sv * (float)k) : sinf(sv * (float)(k - 3));
            v5[(size_t)(bm + row_l) * 5 + t5] = r;
        }
    }
}

// ---------------- final: out[b,o] = sum_i inp[b,i]*w[b,i*64+o] + w[b,1024+o] -
__global__ __launch_bounds__(256)
void final_kernel(const float* __restrict__ w,
                  const float* __restrict__ x,
                  float* __restrict__ out)
{
    __shared__ float inp[4][IN_F];
    const int tid = threadIdx.x;
    const int b0 = blockIdx.x * 4;
    if (tid < 4 * IN_F)
        inp[tid >> 4][tid & 15] = x[(size_t)(b0 + (tid >> 4)) * XCOLS + (tid & 15)];
    __syncthreads();

    const int r = tid >> 6;
    const int o = tid & 63;
    const int b = b0 + r;
    const float* wr = w + (size_t)b * NGRP;
    float accum = wr[1024 + o];
    #pragma unroll
    for (int i = 0; i < IN_F; ++i)
        accum = fmaf(inp[r][i], wr[i * 64 + o], accum);
    out[(size_t)b * 64 + o] = accum;
}

// ----------------------------- launch ---------------------------------------
extern "C" void kernel_launch(void* const* d_in, const int* in_sizes, int n_in,
                              void* d_out, int out_size)
{
    const float* x  = (const float*)d_in[0];
    const float* W1 = (const float*)d_in[1];
    const float* b1 = (const float*)d_in[2];
    const float* W2 = (const float*)d_in[3];
    const float* b2 = (const float*)d_in[4];
    const float* W3 = (const float*)d_in[5];
    const float* b3 = (const float*)d_in[6];
    float* out = (float*)d_out;

    __half *zhi, *zlo, *w1t, *h1h, *h2h, *w2th, *w3th;
    float *w3t12, *bias5, *wbuf, *v5;
    cudaGetSymbolAddress((void**)&zhi,  g_zhi);
    cudaGetSymbolAddress((void**)&zlo,  g_zlo);
    cudaGetSymbolAddress((void**)&w1t,  g_w1t);
    cudaGetSymbolAddress((void**)&h1h,  g_h1h);
    cudaGetSymbolAddress((void**)&h2h,  g_h2h);
    cudaGetSymbolAddress((void**)&w2th, g_w2th);
    cudaGetSymbolAddress((void**)&w3th, g_w3th);
    cudaGetSymbolAddress((void**)&w3t12, g_w3t12);
    cudaGetSymbolAddress((void**)&bias5, g_bias5);
    cudaGetSymbolAddress((void**)&wbuf, g_w);
    cudaGetSymbolAddress((void**)&v5,  g_v5);

    const int SM_2P = 3 * 384 * ROWB1;   // 165888
    const int SM_1P = 3 * 256 * ROWB1;   // 110592

    static bool init_done = false;
    static cudaStream_t s2;
    static cudaEvent_t evFork, evJoin;
    if (!init_done) {
        cudaFuncSetAttribute(gemm_f16<1>, cudaFuncAttributeMaxDynamicSharedMemorySize, SM_2P);
        cudaFuncSetAttribute(gemm_f16<0>, cudaFuncAttributeMaxDynamicSharedMemorySize, SM_1P);
        cudaFuncSetAttribute(gemm_w, cudaFuncAttributeMaxDynamicSharedMemorySize, W_SMEM);
        cudaStreamCreateWithFlags(&s2, cudaStreamNonBlocking);
        cudaEventCreateWithFlags(&evFork, cudaEventDisableTiming);
        cudaEventCreateWithFlags(&evJoin, cudaEventDisableTiming);
        init_done = true;
    }

    // ---- fork: W3 prep on side stream, hidden behind h1/h2 chain ----
    cudaEventRecord(evFork, 0);
    cudaStreamWaitEvent(s2, evFork, 0);

    transpose_h<<<dim3((MK + 31) / 32, (CS + 31) / 32), dim3(32, 8), 0, s2>>>(
        W3, CS, CS, MK, w3th, CSP, 1);
    gather_tail<<<(CS * 12 + 255) / 256, 256, 0, s2>>>(W3, b3, w3t12, bias5);
    cudaEventRecord(evJoin, s2);

    // ---- main stream: prep needed by h1/h2, then the GEMM chain ----
    transpose_h<<<dim3((CS + 31) / 32, (HID + 31) / 32), dim3(32, 8)>>>(
        W2, HID, CS, CS, w2th, HID, 0);
    transpose_h<<<dim3((HID + 31) / 32, (LAT + 31) / 32), dim3(32, 8)>>>(
        W1, LAT, HID, HID, w1t, LAT, 0);
    zprep<<<(B_SZ * LAT + 255) / 256, 256>>>(x, zhi, zlo);

    // 1) h1 = tanh(z @ W1 + b1): 2-pass (exact z), K=128
    gemm_f16<1><<<dim3(HID / 128, B_SZ / 128), 256, SM_2P>>>(
        zhi, zlo, LAT, w1t, LAT, LAT / 64, b1, h1h, HID, HID);

    // 2) h2 = tanh(h1 @ W2 + b2): 1-pass, K=1024
    gemm_f16<0><<<dim3(CSP / 128, B_SZ / 128), 256, SM_1P>>>(
        h1h, nullptr, HID, w2th, HID, HID / 64, b2, h2h, CSP, CS);

    // ---- join: W3 prep must be complete before tail/big GEMM ----
    cudaStreamWaitEvent(0, evJoin, 0);

    // 3) tail mini-GEMM -> v5 (256 blocks)
    tail_gemm<<<B_SZ / 32, 256>>>(h2h, w3t12, b3, x, v5);

    // 4) big GEMM + fused group-of-5 reduction -> w[B][1088]  (round-10 config)
    gemm_w<<<dim3(MK5 / 160, B_SZ / 256), 512, W_SMEM>>>(
        h2h, w3th, bias5, v5, wbuf);

    // 5) adaptive 16->64 linear from fused weights
    final_kernel<<<B_SZ / 4, 256>>>(wbuf, x, out);
}

// round 13
// speedup vs baseline: 1.1186x; 1.0070x over previous
#include <cuda_runtime.h>
#include <cuda_fp16.h>
#include <math.h>
#include <stdint.h>

// ---------------- problem constants ----------------
#define B_SZ   8192
#define XCOLS  145
#define IN_F   16
#define LAT    128
#define HID    1024
#define CS     6540     // (M+2)*K
#define CSP    6656     // CS padded to 256
#define MK     6528     // M*K
#define MK5    5440     // compacted (drop k%6==3, v==0); = 34*160
#define NGRP   1088     // MK5/5
#define NKCS   103      // ceil(CS/64): K-chunks actually needed (pads zero)

// ---------------- scratch (zero-initialized device globals) -----------------
__device__ __half g_zhi [(size_t)B_SZ * LAT];
__device__ __half g_zlo [(size_t)B_SZ * LAT];
__device__ __half g_w1t [(size_t)HID * LAT];
__device__ __half g_h1h [(size_t)B_SZ * HID];
__device__ __half g_h2h [(size_t)B_SZ * CSP];     // pads stay zero
__device__ __half g_w2th[(size_t)CSP * HID];
__device__ __half g_w3th[(size_t)MK5 * CSP];      // compact, K-pads zero
__device__ float  g_w3t12[(size_t)12 * CSP];      // tail cols, pads zero
__device__ float  g_bias5[(size_t)MK5];           // expanded b3 per compact col
__device__ float  g_w   [(size_t)B_SZ * NGRP];    // fused weights
__device__ float  g_v5  [(size_t)B_SZ * 5];

// ---------------- low-level helpers ----------------
__device__ __forceinline__ uint32_t smem_u32(const void* p) {
    uint32_t a;
    asm("{ .reg .u64 t; cvta.to.shared.u64 t, %1; cvt.u32.u64 %0, t; }" : "=r"(a) : "l"(p));
    return a;
}
__device__ __forceinline__ void cpa16(uint32_t dst, const void* src) {
    asm volatile("cp.async.cg.shared.global [%0], [%1], 16;" :: "r"(dst), "l"(src));
}
#define CP_COMMIT() asm volatile("cp.async.commit_group;" ::: "memory")
#define CP_WAIT2()  asm volatile("cp.async.wait_group 2;" ::: "memory")
#define CP_WAIT0()  asm volatile("cp.async.wait_group 0;" ::: "memory")

__device__ __forceinline__ void ldsm4(uint32_t& r0, uint32_t& r1, uint32_t& r2, uint32_t& r3,
                                      uint32_t addr) {
    asm volatile("ldmatrix.sync.aligned.m8n8.x4.shared.b16 {%0,%1,%2,%3}, [%4];"
                 : "=r"(r0), "=r"(r1), "=r"(r2), "=r"(r3) : "r"(addr));
}
__device__ __forceinline__ void mma_f16(float* c, const uint32_t* a, uint32_t b0, uint32_t b1) {
    asm volatile(
        "mma.sync.aligned.m16n8k16.row.col.f32.f16.f16.f32 "
        "{%0,%1,%2,%3}, {%4,%5,%6,%7}, {%8,%9}, {%0,%1,%2,%3};"
        : "+f"(c[0]), "+f"(c[1]), "+f"(c[2]), "+f"(c[3])
        : "r"(a[0]), "r"(a[1]), "r"(a[2]), "r"(a[3]), "r"(b0), "r"(b1));
}

// ============================================================================
// GEMM (h1 / h2): fp16 HMMA f32-acc, tile 128x128, BK=64, 3 stages, 256 thr.
// TWOPASS: A = Ahi + Alo.  out fp16 = tanh(acc + bias[col])
// ============================================================================
#define ROWB1 144

template<int TWOPASS>
__global__ __launch_bounds__(256, TWOPASS ? 1 : 2)
void gemm_f16(const __half* __restrict__ A, const __half* __restrict__ Alo, int lda,
              const __half* __restrict__ B, int ldb, int nk,
              const float* __restrict__ bias,
              __half* __restrict__ outp, int ldo, int Nlimit)
{
    constexpr int ALO_OFF = 128 * ROWB1;
    constexpr int B_OFF   = (TWOPASS ? 256 : 128) * ROWB1;
    constexpr int STG     = (TWOPASS ? 384 : 256) * ROWB1;

    extern __shared__ char smem[];
    const uint32_t sbase = smem_u32(smem);
    const int tid  = threadIdx.x;
    const int lane = tid & 31;
    const int wid  = tid >> 5;
    const int warp_m = wid & 3;
    const int warp_n = wid >> 2;
    const int bm = blockIdx.y * 128;
    const int bn = blockIdx.x * 128;

    const int lrow = tid >> 1;
    const int lhalf = tid & 1;
    const char* aSrc  = (const char*)(A + (size_t)(bm + lrow) * lda) + lhalf * 64;
    const char* alSrc = (const char*)(Alo + (size_t)(bm + lrow) * lda) + lhalf * 64;
    const char* bSrc  = (const char*)(B + (size_t)(bn + lrow) * ldb) + lhalf * 64;
    const uint32_t dA = lrow * ROWB1 + lhalf * 64;

    float acc[2][8][4];
    #pragma unroll
    for (int i = 0; i < 2; ++i)
        #pragma unroll
        for (int j = 0; j < 8; ++j)
            #pragma unroll
            for (int l = 0; l < 4; ++l) acc[i][j][l] = 0.f;

    auto load_stage = [&](int s, int kc) {
        const uint32_t sA = sbase + s * STG;
        const size_t kb = (size_t)kc * 128;
        #pragma unroll
        for (int j = 0; j < 4; ++j) {
            cpa16(sA + dA + j * 16,         aSrc + kb + j * 16);
            if (TWOPASS) cpa16(sA + ALO_OFF + dA + j * 16, alSrc + kb + j * 16);
            cpa16(sA + B_OFF + dA + j * 16, bSrc + kb + j * 16);
        }
    };

    load_stage(0, 0); CP_COMMIT();
    if (nk > 1) load_stage(1, 1);
    CP_COMMIT();

    const int l15  = lane & 15;
    const int lksl = (lane >> 4) & 1;

    for (int k = 0; k < nk; ++k) {
        const int fetch = k + 2;
        if (fetch < nk) load_stage(fetch % 3, fetch);
        CP_COMMIT();
        CP_WAIT2();
        __syncthreads();

        const uint32_t sA = sbase + (k % 3) * STG;
        const uint32_t sB = sA + B_OFF;

        #pragma unroll
        for (int ks = 0; ks < 4; ++ks) {
            const uint32_t koff = ks * 32 + lksl * 16;
            uint32_t a[2][4], al[2][4];
            #pragma unroll
            for (int mt = 0; mt < 2; ++mt) {
                uint32_t ra = sA + (uint32_t)(warp_m * 32 + mt * 16 + l15) * ROWB1 + koff;
                ldsm4(a[mt][0], a[mt][1], a[mt][2], a[mt][3], ra);
                if (TWOPASS)
                    ldsm4(al[mt][0], al[mt][1], al[mt][2], al[mt][3], ra + ALO_OFF);
            }
            uint32_t bh[2][4];
            {
                uint32_t rb = sB + (uint32_t)(warp_n * 64 + l15) * ROWB1 + koff;
                ldsm4(bh[0][0], bh[0][1], bh[0][2], bh[0][3], rb);
            }
            #pragma unroll
            for (int g = 0; g < 4; ++g) {
                const int cur = g & 1, nxt = cur ^ 1;
                if (g < 3) {
                    uint32_t rb = sB + (uint32_t)(warp_n * 64 + (g + 1) * 16 + l15) * ROWB1 + koff;
                    ldsm4(bh[nxt][0], bh[nxt][1], bh[nxt][2], bh[nxt][3], rb);
                }
                float* c00 = acc[0][2 * g];
                float* c01 = acc[0][2 * g + 1];
                float* c10 = acc[1][2 * g];
                float* c11 = acc[1][2 * g + 1];
                mma_f16(c00, a[0], bh[cur][0], bh[cur][2]);
                mma_f16(c01, a[0], bh[cur][1], bh[cur][3]);
                mma_f16(c10, a[1], bh[cur][0], bh[cur][2]);
                mma_f16(c11, a[1], bh[cur][1], bh[cur][3]);
                if (TWOPASS) {
                    mma_f16(c00, al[0], bh[cur][0], bh[cur][2]);
                    mma_f16(c01, al[0], bh[cur][1], bh[cur][3]);
                    mma_f16(c10, al[1], bh[cur][0], bh[cur][2]);
                    mma_f16(c11, al[1], bh[cur][1], bh[cur][3]);
                }
            }
        }
        __syncthreads();
    }

    #pragma unroll
    for (int mt = 0; mt < 2; ++mt) {
        #pragma unroll
        for (int h = 0; h < 2; ++h) {
            const int row = bm + warp_m * 32 + mt * 16 + (lane >> 2) + h * 8;
            #pragma unroll
            for (int nt = 0; nt < 8; ++nt) {
                const int col = bn + warp_n * 64 + nt * 8 + ((lane & 3) << 1);
                if (col < Nlimit) {
                    float t0 = tanhf(acc[mt][nt][h * 2 + 0] + bias[col]);
                    float t1 = tanhf(acc[mt][nt][h * 2 + 1] + bias[col + 1]);
                    __half2 hp;
                    hp.x = __float2half(t0);
                    hp.y = __float2half(t1);
                    *reinterpret_cast<__half2*>(outp + (size_t)row * ldo + col) = hp;
                }
            }
        }
    }
}

// ============================================================================
// Big GEMM + fused group-of-5 reduction: tile 256x160, BK=64, 3 stages, 512thr.
// nk = NKCS = 103 (chunk 103 would be all-zero pads).
// w[b, m] = sum_{j5} (acc[b, m*5+j5] + bias5[m*5+j5]) * v5[b, j5]
// ============================================================================
#define W_BOFF (256 * ROWB1)            // 36864
#define W_STG  ((256 + 160) * ROWB1)    // 59904
#define W_SMEM (3 * W_STG)              // 179712
#define W_PADN 164

__global__ __launch_bounds__(512, 1)
void gemm_w(const __half* __restrict__ A, const __half* __restrict__ B,
            const float* __restrict__ bias5, const float* __restrict__ v5,
            float* __restrict__ w)
{
    extern __shared__ char smem[];
    const uint32_t sbase = smem_u32(smem);
    const int tid  = threadIdx.x;
    const int lane = tid & 31;
    const int wid  = tid >> 5;
    const int warp_m = wid & 7;           // 0..7 (32 rows each)
    const int warp_n = wid >> 3;          // 0..1 (80 cols each)
    const int bm = blockIdx.y * 256;
    const int bn = blockIdx.x * 160;

    const bool isA = tid < 256;
    const int ltid = isA ? tid : tid - 256;
    const int lrow = ltid >> 3;
    const int lcol = ltid & 7;
    const char* gsrc = isA
        ? (const char*)(A + (size_t)(bm + lrow) * CSP) + lcol * 16
        : (const char*)(B + (size_t)(bn + lrow) * CSP) + lcol * 16;
    const uint32_t dst0 = (isA ? 0u : (uint32_t)W_BOFF) + lrow * ROWB1 + lcol * 16;
    const size_t gstr = (size_t)32 * CSP * 2;

    float acc[2][10][4];
    #pragma unroll
    for (int i = 0; i < 2; ++i)
        #pragma unroll
        for (int j = 0; j < 10; ++j)
            #pragma unroll
            for (int l = 0; l < 4; ++l) acc[i][j][l] = 0.f;

    auto load_stage = [&](int s, int kc) {
        const uint32_t base = sbase + s * W_STG + dst0;
        const char* g = gsrc + (size_t)kc * 128;
        if (isA) {
            #pragma unroll
            for (int t = 0; t < 8; ++t)
                cpa16(base + t * (32 * ROWB1), g + t * gstr);
        } else {
            #pragma unroll
            for (int t = 0; t < 5; ++t)
                cpa16(base + t * (32 * ROWB1), g + t * gstr);
        }
    };

    const int nk = NKCS;   // 103 (covers k < 6592 >= CS; remainder is zero pad)
    load_stage(0, 0); CP_COMMIT();
    load_stage(1, 1); CP_COMMIT();

    const int l15  = lane & 15;
    const int lksl = (lane >> 4) & 1;

    for (int k = 0; k < nk; ++k) {
        const int fetch = k + 2;
        if (fetch < nk) load_stage(fetch % 3, fetch);
        CP_COMMIT();
        CP_WAIT2();
        __syncthreads();

        const uint32_t sA = sbase + (k % 3) * W_STG;
        const uint32_t sB = sA + W_BOFF;

        #pragma unroll
        for (int ks = 0; ks < 4; ++ks) {
            const uint32_t koff = ks * 32 + lksl * 16;
            uint32_t a[2][4];
            #pragma unroll
            for (int mt = 0; mt < 2; ++mt) {
                uint32_t ra = sA + (uint32_t)(warp_m * 32 + mt * 16 + l15) * ROWB1 + koff;
                ldsm4(a[mt][0], a[mt][1], a[mt][2], a[mt][3], ra);
            }
            uint32_t bh[2][4];
            {
                uint32_t rb = sB + (uint32_t)(warp_n * 80 + l15) * ROWB1 + koff;
                ldsm4(bh[0][0], bh[0][1], bh[0][2], bh[0][3], rb);
            }
            #pragma unroll
            for (int g = 0; g < 5; ++g) {
                const int cur = g & 1, nxt = cur ^ 1;
                if (g < 4) {
                    uint32_t rb = sB + (uint32_t)(warp_n * 80 + (g + 1) * 16 + l15) * ROWB1 + koff;
                    ldsm4(bh[nxt][0], bh[nxt][1], bh[nxt][2], bh[nxt][3], rb);
                }
                mma_f16(acc[0][2 * g],     a[0], bh[cur][0], bh[cur][2]);
                mma_f16(acc[0][2 * g + 1], a[0], bh[cur][1], bh[cur][3]);
                mma_f16(acc[1][2 * g],     a[1], bh[cur][0], bh[cur][2]);
                mma_f16(acc[1][2 * g + 1], a[1], bh[cur][1], bh[cur][3]);
            }
        }
        __syncthreads();
    }

    // ---------------- fused epilogue: stage tile, reduce groups of 5 --------
    CP_WAIT0();
    __syncthreads();

    float* stg = reinterpret_cast<float*>(smem);          // [256][164]
    float* v5s = stg + 256 * W_PADN;                       // [256][5]
    float* b5s = v5s + 256 * 5;                            // [160]

    #pragma unroll
    for (int mt = 0; mt < 2; ++mt) {
        #pragma unroll
        for (int h = 0; h < 2; ++h) {
            const int row = warp_m * 32 + mt * 16 + (lane >> 2) + h * 8;
            #pragma unroll
            for (int nt = 0; nt < 10; ++nt) {
                const int col = warp_n * 80 + nt * 8 + ((lane & 3) << 1);
                stg[row * W_PADN + col]     = acc[mt][nt][h * 2 + 0];
                stg[row * W_PADN + col + 1] = acc[mt][nt][h * 2 + 1];
            }
        }
    }
    for (int i = tid; i < 256 * 5; i += 512) v5s[i] = v5[(size_t)bm * 5 + i];
    if (tid < 160) b5s[tid] = bias5[bn + tid];
    __syncthreads();

    const int gbase = blockIdx.x * 32;
    for (int i = tid; i < 256 * 32; i += 512) {
        const int row = i >> 5, grp = i & 31;
        const float* p  = stg + row * W_PADN + grp * 5;
        const float* vv = v5s + row * 5;
        const float* bb = b5s + grp * 5;
        float s = (p[0] + bb[0]) * vv[0];
        s = fmaf(p[1] + bb[1], vv[1], s);
        s = fmaf(p[2] + bb[2], vv[2], s);
        s = fmaf(p[3] + bb[3], vv[3], s);
        s = fmaf(p[4] + bb[4], vv[4], s);
        w[(size_t)(bm + row) * NGRP + gbase + grp] = s;
    }
}

// ---------------- transpose + fp16 (optionally compact k%6==3) --------------
__global__ __launch_bounds__(256)
void transpose_h(const float* __restrict__ W, int R, int Cstride, int nlimit,
                 __half* __restrict__ Thi, int ldt, int compact)
{
    __shared__ float ts[32][33];
    const int tx = threadIdx.x, ty = threadIdx.y;
    const int n0 = blockIdx.x * 32, k0 = blockIdx.y * 32;
    #pragma unroll
    for (int i = 0; i < 32; i += 8) {
        int k = k0 + ty + i, n = n0 + tx;
        ts[ty + i][tx] = (k < R && n < nlimit) ? W[(size_t)k * Cstride + n] : 0.f;
    }
    __syncthreads();
    #pragma unroll
    for (int i = 0; i < 32; i += 8) {
        int n = n0 + ty + i, k = k0 + tx;
        if (n < nlimit && k < R) {
            int np = n;
            if (compact) {
                int r6 = n % 6;
                if (r6 == 3) continue;
                np = (n / 6) * 5 + (r6 < 3 ? r6 : r6 - 1);
            }
            Thi[(size_t)np * ldt + k] = __float2half(ts[tx][ty + i]);
        }
    }
}

// ---------------- gather W3 tail cols + bias5 --------------------------------
__global__ __launch_bounds__(256)
void gather_tail(const float* __restrict__ W3, const float* __restrict__ b3,
                 float* __restrict__ w3t12, float* __restrict__ bias5)
{
    int i = blockIdx.x * 256 + threadIdx.x;
    if (i < CS * 12) {
        int c = i / 12, j = i % 12;
        w3t12[(size_t)j * CSP + c] = W3[(size_t)c * CS + MK + j];
    }
    if (i < MK5) {
        int m6 = i / 5, j5 = i - m6 * 5;
        int kk = (j5 < 3) ? j5 : j5 + 1;
        bias5[i] = b3[m6 * 6 + kk];
    }
}

// ---------------- z -> fp16 hi/lo (contiguous [B][128]) ---------------------
__global__ __launch_bounds__(256)
void zprep(const float* __restrict__ x, __half* __restrict__ zhi, __half* __restrict__ zlo)
{
    int i = blockIdx.x * 256 + threadIdx.x;
    if (i < B_SZ * LAT) {
        int b = i >> 7, c = i & 127;
        float v = x[(size_t)b * XCOLS + (IN_F + 1) + c];
        __half h = __float2half(v);
        zhi[i] = h;
        zlo[i] = __float2half(v - __half2float(h));
    }
}

// ---------------- tail GEMM: 32 rows/block, 8 thr/row, shfl reduce ----------
__global__ __launch_bounds__(256)
void tail_gemm(const __half* __restrict__ h2h,
               const float* __restrict__ w3t12,
               const float* __restrict__ b3,
               const float* __restrict__ x,
               float* __restrict__ v5)
{
    __shared__ __half h2s[32 * 72];
    __shared__ float  w3s[64 * 12];

    const int tid = threadIdx.x;
    const int bm = blockIdx.x * 32;
    const int row_l = tid >> 3;
    const int ksub = tid & 7;

    float acc[12];
    #pragma unroll
    for (int j = 0; j < 12; ++j) acc[j] = 0.f;

    for (int kc = 0; kc < NKCS; ++kc) {
        {
            uint4 v = *reinterpret_cast<const uint4*>(
                h2h + (size_t)(bm + row_l) * CSP + kc * 64 + ksub * 8);
            *reinterpret_cast<uint4*>(&h2s[row_l * 72 + ksub * 8]) = v;
        }
        for (int i = tid; i < 64 * 12; i += 256) {
            int k = i / 12, j = i % 12;
            w3s[i] = w3t12[(size_t)j * CSP + kc * 64 + k];
        }
        __syncthreads();

        #pragma unroll
        for (int kk = 0; kk < 8; ++kk) {
            int k = kk * 8 + ksub;
            float hv = __half2float(h2s[row_l * 72 + k]);
            #pragma unroll
            for (int j = 0; j < 12; ++j)
                acc[j] = fmaf(hv, w3s[k * 12 + j], acc[j]);
        }
        __syncthreads();
    }

    #pragma unroll
    for (int j = 0; j < 12; ++j) {
        #pragma unroll
        for (int d = 4; d > 0; d >>= 1)
            acc[j] += __shfl_down_sync(0xffffffffu, acc[j], d);
    }

    if (ksub == 0) {
        float s = x[(size_t)(B_SZ - 1) * XCOLS + IN_F];
        float dt[12];
        #pragma unroll
        for (int j = 0; j < 12; ++j) dt[j] = acc[j] + b3[MK + j];
        #pragma unroll
        for (int t5 = 0; t5 < 5; ++t5) {
            int k = (t5 < 3) ? t5 : t5 + 1;
            float sv = fmaf(s, dt[k], dt[k + 6]);
            float r = (k < 3) ? cosf(sv * (float)k) : sinf(sv * (float)(k - 3));
            v5[(size_t)(bm + row_l) * 5 + t5] = r;
        }
    }
}

// ---------------- final: out[b,o] = sum_i inp[b,i]*w[b,i*64+o] + w[b,1024+o] -
__global__ __launch_bounds__(256)
void final_kernel(const float* __restrict__ w,
                  const float* __restrict__ x,
                  float* __restrict__ out)
{
    __shared__ float inp[4][IN_F];
    const int tid = threadIdx.x;
    const int b0 = blockIdx.x * 4;
    if (tid < 4 * IN_F)
        inp[tid >> 4][tid & 15] = x[(size_t)(b0 + (tid >> 4)) * XCOLS + (tid & 15)];
    __syncthreads();

    const int r = tid >> 6;
    const int o = tid & 63;
    const int b = b0 + r;
    const float* wr = w + (size_t)b * NGRP;
    float accum = wr[1024 + o];
    #pragma unroll
    for (int i = 0; i < IN_F; ++i)
        accum = fmaf(inp[r][i], wr[i * 64 + o], accum);
    out[(size_t)b * 64 + o] = accum;
}

// ----------------------------- launch ---------------------------------------
extern "C" void kernel_launch(void* const* d_in, const int* in_sizes, int n_in,
                              void* d_out, int out_size)
{
    const float* x  = (const float*)d_in[0];
    const float* W1 = (const float*)d_in[1];
    const float* b1 = (const float*)d_in[2];
    const float* W2 = (const float*)d_in[3];
    const float* b2 = (const float*)d_in[4];
    const float* W3 = (const float*)d_in[5];
    const float* b3 = (const float*)d_in[6];
    float* out = (float*)d_out;

    __half *zhi, *zlo, *w1t, *h1h, *h2h, *w2th, *w3th;
    float *w3t12, *bias5, *wbuf, *v5;
    cudaGetSymbolAddress((void**)&zhi,  g_zhi);
    cudaGetSymbolAddress((void**)&zlo,  g_zlo);
    cudaGetSymbolAddress((void**)&w1t,  g_w1t);
    cudaGetSymbolAddress((void**)&h1h,  g_h1h);
    cudaGetSymbolAddress((void**)&h2h,  g_h2h);
    cudaGetSymbolAddress((void**)&w2th, g_w2th);
    cudaGetSymbolAddress((void**)&w3th, g_w3th);
    cudaGetSymbolAddress((void**)&w3t12, g_w3t12);
    cudaGetSymbolAddress((void**)&bias5, g_bias5);
    cudaGetSymbolAddress((void**)&wbuf, g_w);
    cudaGetSymbolAddress((void**)&v5,  g_v5);

    const int SM_2P = 3 * 384 * ROWB1;   // 165888
    const int SM_1P = 3 * 256 * ROWB1;   // 110592

    static bool attr_set = false;
    if (!attr_set) {
        cudaFuncSetAttribute(gemm_f16<1>, cudaFuncAttributeMaxDynamicSharedMemorySize, SM_2P);
        cudaFuncSetAttribute(gemm_f16<0>, cudaFuncAttributeMaxDynamicSharedMemorySize, SM_1P);
        cudaFuncSetAttribute(gemm_w, cudaFuncAttributeMaxDynamicSharedMemorySize, W_SMEM);
        attr_set = true;
    }

    // 0) prep (serial — fork/event machinery was measured neutral)
    transpose_h<<<dim3((CS + 31) / 32, (HID + 31) / 32), dim3(32, 8)>>>(
        W2, HID, CS, CS, w2th, HID, 0);
    transpose_h<<<dim3((MK + 31) / 32, (CS + 31) / 32), dim3(32, 8)>>>(
        W3, CS, CS, MK, w3th, CSP, 1);
    transpose_h<<<dim3((HID + 31) / 32, (LAT + 31) / 32), dim3(32, 8)>>>(
        W1, LAT, HID, HID, w1t, LAT, 0);
    gather_tail<<<(CS * 12 + 255) / 256, 256>>>(W3, b3, w3t12, bias5);
    zprep<<<(B_SZ * LAT + 255) / 256, 256>>>(x, zhi, zlo);

    // 1) h1 = tanh(z @ W1 + b1): 2-pass (exact z), K=128
    gemm_f16<1><<<dim3(HID / 128, B_SZ / 128), 256, SM_2P>>>(
        zhi, zlo, LAT, w1t, LAT, LAT / 64, b1, h1h, HID, HID);

    // 2) h2 = tanh(h1 @ W2 + b2): 1-pass, K=1024
    gemm_f16<0><<<dim3(CSP / 128, B_SZ / 128), 256, SM_1P>>>(
        h1h, nullptr, HID, w2th, HID, HID / 64, b2, h2h, CSP, CS);

    // 3) tail mini-GEMM -> v5 (256 blocks, 103 K-chunks)
    tail_gemm<<<B_SZ / 32, 256>>>(h2h, w3t12, b3, x, v5);

    // 4) big GEMM + fused group-of-5 reduction -> w[B][1088] (103 K-chunks)
    gemm_w<<<dim3(MK5 / 160, B_SZ / 256), 512, W_SMEM>>>(
        h2h, w3th, bias5, v5, wbuf);

    // 5) adaptive 16->64 linear from fused weights
    final_kernel<<<B_SZ / 4, 256>>>(wbuf, x, out);
}

// round 14
// speedup vs baseline: 1.1255x; 1.0063x over previous
#include <cuda_runtime.h>
#include <cuda_fp16.h>
#include <math.h>
#include <stdint.h>

// ---------------- problem constants ----------------
#define B_SZ   8192
#define XCOLS  145
#define IN_F   16
#define LAT    128
#define HID    1024
#define CS     6540     // (M+2)*K
#define CSP    6656     // CS padded to 256
#define MK     6528     // M*K
#define MK5    5440     // compacted (drop k%6==3, v==0); = 34*160
#define NGRP   1088     // MK5/5
#define NKCS   103      // ceil(CS/64): K-chunks actually needed (pads zero)

// ---------------- scratch (zero-initialized device globals) -----------------
__device__ __half g_zhi [(size_t)B_SZ * LAT];
__device__ __half g_zlo [(size_t)B_SZ * LAT];
__device__ __half g_w1t [(size_t)HID * LAT];
__device__ __half g_h1h [(size_t)B_SZ * HID];
__device__ __half g_h2h [(size_t)B_SZ * CSP];     // pads stay zero
__device__ __half g_w2th[(size_t)CSP * HID];
__device__ __half g_w3th[(size_t)MK5 * CSP];      // compact, K-pads zero
__device__ float  g_w3t12[(size_t)12 * CSP];      // tail cols, pads zero
__device__ float  g_bias5[(size_t)MK5];           // expanded b3 per compact col
__device__ float  g_w   [(size_t)B_SZ * NGRP];    // fused weights
__device__ float  g_v5  [(size_t)B_SZ * 5];

// ---------------- low-level helpers ----------------
__device__ __forceinline__ uint32_t smem_u32(const void* p) {
    uint32_t a;
    asm("{ .reg .u64 t; cvta.to.shared.u64 t, %1; cvt.u32.u64 %0, t; }" : "=r"(a) : "l"(p));
    return a;
}
__device__ __forceinline__ void cpa16(uint32_t dst, const void* src) {
    asm volatile("cp.async.cg.shared.global [%0], [%1], 16;" :: "r"(dst), "l"(src));
}
#define CP_COMMIT() asm volatile("cp.async.commit_group;" ::: "memory")
#define CP_WAIT2()  asm volatile("cp.async.wait_group 2;" ::: "memory")
#define CP_WAIT0()  asm volatile("cp.async.wait_group 0;" ::: "memory")

__device__ __forceinline__ void ldsm4(uint32_t& r0, uint32_t& r1, uint32_t& r2, uint32_t& r3,
                                      uint32_t addr) {
    asm volatile("ldmatrix.sync.aligned.m8n8.x4.shared.b16 {%0,%1,%2,%3}, [%4];"
                 : "=r"(r0), "=r"(r1), "=r"(r2), "=r"(r3) : "r"(addr));
}
__device__ __forceinline__ void mma_f16(float* c, const uint32_t* a, uint32_t b0, uint32_t b1) {
    asm volatile(
        "mma.sync.aligned.m16n8k16.row.col.f32.f16.f16.f32 "
        "{%0,%1,%2,%3}, {%4,%5,%6,%7}, {%8,%9}, {%0,%1,%2,%3};"
        : "+f"(c[0]), "+f"(c[1]), "+f"(c[2]), "+f"(c[3])
        : "r"(a[0]), "r"(a[1]), "r"(a[2]), "r"(a[3]), "r"(b0), "r"(b1));
}
// HW tanh (MUFU.TANH, sm_75+, 1 instruction; rel err ~2^-11 << fp16 store rounding path)
__device__ __forceinline__ float tanh_hw(float x) {
    float y;
    asm("tanh.approx.f32 %0, %1;" : "=f"(y) : "f"(x));
    return y;
}

// ============================================================================
// GEMM (h1 / h2): fp16 HMMA f32-acc, tile 128x128, BK=64, 3 stages, 256 thr.
// TWOPASS: A = Ahi + Alo.  out fp16 = tanh_hw(acc + bias[col])
// ============================================================================
#define ROWB1 144

template<int TWOPASS>
__global__ __launch_bounds__(256, TWOPASS ? 1 : 2)
void gemm_f16(const __half* __restrict__ A, const __half* __restrict__ Alo, int lda,
              const __half* __restrict__ B, int ldb, int nk,
              const float* __restrict__ bias,
              __half* __restrict__ outp, int ldo, int Nlimit)
{
    constexpr int ALO_OFF = 128 * ROWB1;
    constexpr int B_OFF   = (TWOPASS ? 256 : 128) * ROWB1;
    constexpr int STG     = (TWOPASS ? 384 : 256) * ROWB1;

    extern __shared__ char smem[];
    const uint32_t sbase = smem_u32(smem);
    const int tid  = threadIdx.x;
    const int lane = tid & 31;
    const int wid  = tid >> 5;
    const int warp_m = wid & 3;
    const int warp_n = wid >> 2;
    const int bm = blockIdx.y * 128;
    const int bn = blockIdx.x * 128;

    const int lrow = tid >> 1;
    const int lhalf = tid & 1;
    const char* aSrc  = (const char*)(A + (size_t)(bm + lrow) * lda) + lhalf * 64;
    const char* alSrc = (const char*)(Alo + (size_t)(bm + lrow) * lda) + lhalf * 64;
    const char* bSrc  = (const char*)(B + (size_t)(bn + lrow) * ldb) + lhalf * 64;
    const uint32_t dA = lrow * ROWB1 + lhalf * 64;

    float acc[2][8][4];
    #pragma unroll
    for (int i = 0; i < 2; ++i)
        #pragma unroll
        for (int j = 0; j < 8; ++j)
            #pragma unroll
            for (int l = 0; l < 4; ++l) acc[i][j][l] = 0.f;

    auto load_stage = [&](int s, int kc) {
        const uint32_t sA = sbase + s * STG;
        const size_t kb = (size_t)kc * 128;
        #pragma unroll
        for (int j = 0; j < 4; ++j) {
            cpa16(sA + dA + j * 16,         aSrc + kb + j * 16);
            if (TWOPASS) cpa16(sA + ALO_OFF + dA + j * 16, alSrc + kb + j * 16);
            cpa16(sA + B_OFF + dA + j * 16, bSrc + kb + j * 16);
        }
    };

    load_stage(0, 0); CP_COMMIT();
    if (nk > 1) load_stage(1, 1);
    CP_COMMIT();

    const int l15  = lane & 15;
    const int lksl = (lane >> 4) & 1;

    for (int k = 0; k < nk; ++k) {
        const int fetch = k + 2;
        if (fetch < nk) load_stage(fetch % 3, fetch);
        CP_COMMIT();
        CP_WAIT2();
        __syncthreads();

        const uint32_t sA = sbase + (k % 3) * STG;
        const uint32_t sB = sA + B_OFF;

        #pragma unroll
        for (int ks = 0; ks < 4; ++ks) {
            const uint32_t koff = ks * 32 + lksl * 16;
            uint32_t a[2][4], al[2][4];
            #pragma unroll
            for (int mt = 0; mt < 2; ++mt) {
                uint32_t ra = sA + (uint32_t)(warp_m * 32 + mt * 16 + l15) * ROWB1 + koff;
                ldsm4(a[mt][0], a[mt][1], a[mt][2], a[mt][3], ra);
                if (TWOPASS)
                    ldsm4(al[mt][0], al[mt][1], al[mt][2], al[mt][3], ra + ALO_OFF);
            }
            uint32_t bh[2][4];
            {
                uint32_t rb = sB + (uint32_t)(warp_n * 64 + l15) * ROWB1 + koff;
                ldsm4(bh[0][0], bh[0][1], bh[0][2], bh[0][3], rb);
            }
            #pragma unroll
            for (int g = 0; g < 4; ++g) {
                const int cur = g & 1, nxt = cur ^ 1;
                if (g < 3) {
                    uint32_t rb = sB + (uint32_t)(warp_n * 64 + (g + 1) * 16 + l15) * ROWB1 + koff;
                    ldsm4(bh[nxt][0], bh[nxt][1], bh[nxt][2], bh[nxt][3], rb);
                }
                float* c00 = acc[0][2 * g];
                float* c01 = acc[0][2 * g + 1];
                float* c10 = acc[1][2 * g];
                float* c11 = acc[1][2 * g + 1];
                mma_f16(c00, a[0], bh[cur][0], bh[cur][2]);
                mma_f16(c01, a[0], bh[cur][1], bh[cur][3]);
                mma_f16(c10, a[1], bh[cur][0], bh[cur][2]);
                mma_f16(c11, a[1], bh[cur][1], bh[cur][3]);
                if (TWOPASS) {
                    mma_f16(c00, al[0], bh[cur][0], bh[cur][2]);
                    mma_f16(c01, al[0], bh[cur][1], bh[cur][3]);
                    mma_f16(c10, al[1], bh[cur][0], bh[cur][2]);
                    mma_f16(c11, al[1], bh[cur][1], bh[cur][3]);
                }
            }
        }
        __syncthreads();
    }

    #pragma unroll
    for (int mt = 0; mt < 2; ++mt) {
        #pragma unroll
        for (int h = 0; h < 2; ++h) {
            const int row = bm + warp_m * 32 + mt * 16 + (lane >> 2) + h * 8;
            #pragma unroll
            for (int nt = 0; nt < 8; ++nt) {
                const int col = bn + warp_n * 64 + nt * 8 + ((lane & 3) << 1);
                if (col < Nlimit) {
                    float t0 = tanh_hw(acc[mt][nt][h * 2 + 0] + bias[col]);
                    float t1 = tanh_hw(acc[mt][nt][h * 2 + 1] + bias[col + 1]);
                    __half2 hp;
                    hp.x = __float2half(t0);
                    hp.y = __float2half(t1);
                    *reinterpret_cast<__half2*>(outp + (size_t)row * ldo + col) = hp;
                }
            }
        }
    }
}

// ============================================================================
// Big GEMM + fused group-of-5 reduction: tile 256x160, BK=64, 3 stages, 512thr.
// nk = NKCS = 103 (chunk 103 would be all-zero pads).
// w[b, m] = sum_{j5} (acc[b, m*5+j5] + bias5[m*5+j5]) * v5[b, j5]
// ============================================================================
#define W_BOFF (256 * ROWB1)            // 36864
#define W_STG  ((256 + 160) * ROWB1)    // 59904
#define W_SMEM (3 * W_STG)              // 179712
#define W_PADN 164

__global__ __launch_bounds__(512, 1)
void gemm_w(const __half* __restrict__ A, const __half* __restrict__ B,
            const float* __restrict__ bias5, const float* __restrict__ v5,
            float* __restrict__ w)
{
    extern __shared__ char smem[];
    const uint32_t sbase = smem_u32(smem);
    const int tid  = threadIdx.x;
    const int lane = tid & 31;
    const int wid  = tid >> 5;
    const int warp_m = wid & 7;           // 0..7 (32 rows each)
    const int warp_n = wid >> 3;          // 0..1 (80 cols each)
    const int bm = blockIdx.y * 256;
    const int bn = blockIdx.x * 160;

    const bool isA = tid < 256;
    const int ltid = isA ? tid : tid - 256;
    const int lrow = ltid >> 3;
    const int lcol = ltid & 7;
    const char* gsrc = isA
        ? (const char*)(A + (size_t)(bm + lrow) * CSP) + lcol * 16
        : (const char*)(B + (size_t)(bn + lrow) * CSP) + lcol * 16;
    const uint32_t dst0 = (isA ? 0u : (uint32_t)W_BOFF) + lrow * ROWB1 + lcol * 16;
    const size_t gstr = (size_t)32 * CSP * 2;

    float acc[2][10][4];
    #pragma unroll
    for (int i = 0; i < 2; ++i)
        #pragma unroll
        for (int j = 0; j < 10; ++j)
            #pragma unroll
            for (int l = 0; l < 4; ++l) acc[i][j][l] = 0.f;

    auto load_stage = [&](int s, int kc) {
        const uint32_t base = sbase + s * W_STG + dst0;
        const char* g = gsrc + (size_t)kc * 128;
        if (isA) {
            #pragma unroll
            for (int t = 0; t < 8; ++t)
                cpa16(base + t * (32 * ROWB1), g + t * gstr);
        } else {
            #pragma unroll
            for (int t = 0; t < 5; ++t)
                cpa16(base + t * (32 * ROWB1), g + t * gstr);
        }
    };

    const int nk = NKCS;   // 103
    load_stage(0, 0); CP_COMMIT();
    load_stage(1, 1); CP_COMMIT();

    const int l15  = lane & 15;
    const int lksl = (lane >> 4) & 1;

    for (int k = 0; k < nk; ++k) {
        const int fetch = k + 2;
        if (fetch < nk) load_stage(fetch % 3, fetch);
        CP_COMMIT();
        CP_WAIT2();
        __syncthreads();

        const uint32_t sA = sbase + (k % 3) * W_STG;
        const uint32_t sB = sA + W_BOFF;

        #pragma unroll
        for (int ks = 0; ks < 4; ++ks) {
            const uint32_t koff = ks * 32 + lksl * 16;
            uint32_t a[2][4];
            #pragma unroll
            for (int mt = 0; mt < 2; ++mt) {
                uint32_t ra = sA + (uint32_t)(warp_m * 32 + mt * 16 + l15) * ROWB1 + koff;
                ldsm4(a[mt][0], a[mt][1], a[mt][2], a[mt][3], ra);
            }
            uint32_t bh[2][4];
            {
                uint32_t rb = sB + (uint32_t)(warp_n * 80 + l15) * ROWB1 + koff;
                ldsm4(bh[0][0], bh[0][1], bh[0][2], bh[0][3], rb);
            }
            #pragma unroll
            for (int g = 0; g < 5; ++g) {
                const int cur = g & 1, nxt = cur ^ 1;
                if (g < 4) {
                    uint32_t rb = sB + (uint32_t)(warp_n * 80 + (g + 1) * 16 + l15) * ROWB1 + koff;
                    ldsm4(bh[nxt][0], bh[nxt][1], bh[nxt][2], bh[nxt][3], rb);
                }
                mma_f16(acc[0][2 * g],     a[0], bh[cur][0], bh[cur][2]);
                mma_f16(acc[0][2 * g + 1], a[0], bh[cur][1], bh[cur][3]);
                mma_f16(acc[1][2 * g],     a[1], bh[cur][0], bh[cur][2]);
                mma_f16(acc[1][2 * g + 1], a[1], bh[cur][1], bh[cur][3]);
            }
        }
        __syncthreads();
    }

    // ---------------- fused epilogue: stage tile, reduce groups of 5 --------
    CP_WAIT0();
    __syncthreads();

    float* stg = reinterpret_cast<float*>(smem);          // [256][164]
    float* v5s = stg + 256 * W_PADN;                       // [256][5]
    float* b5s = v5s + 256 * 5;                            // [160]

    #pragma unroll
    for (int mt = 0; mt < 2; ++mt) {
        #pragma unroll
        for (int h = 0; h < 2; ++h) {
            const int row = warp_m * 32 + mt * 16 + (lane >> 2) + h * 8;
            #pragma unroll
            for (int nt = 0; nt < 10; ++nt) {
                const int col = warp_n * 80 + nt * 8 + ((lane & 3) << 1);
                stg[row * W_PADN + col]     = acc[mt][nt][h * 2 + 0];
                stg[row * W_PADN + col + 1] = acc[mt][nt][h * 2 + 1];
            }
        }
    }
    for (int i = tid; i < 256 * 5; i += 512) v5s[i] = v5[(size_t)bm * 5 + i];
    if (tid < 160) b5s[tid] = bias5[bn + tid];
    __syncthreads();

    const int gbase = blockIdx.x * 32;
    for (int i = tid; i < 256 * 32; i += 512) {
        const int row = i >> 5, grp = i & 31;
        const float* p  = stg + row * W_PADN + grp * 5;
        const float* vv = v5s + row * 5;
        const float* bb = b5s + grp * 5;
        float s = (p[0] + bb[0]) * vv[0];
        s = fmaf(p[1] + bb[1], vv[1], s);
        s = fmaf(p[2] + bb[2], vv[2], s);
        s = fmaf(p[3] + bb[3], vv[3], s);
        s = fmaf(p[4] + bb[4], vv[4], s);
        w[(size_t)(bm + row) * NGRP + gbase + grp] = s;
    }
}

// ---------------- transpose + fp16 (optionally compact k%6==3) --------------
__global__ __launch_bounds__(256)
void transpose_h(const float* __restrict__ W, int R, int Cstride, int nlimit,
                 __half* __restrict__ Thi, int ldt, int compact)
{
    __shared__ float ts[32][33];
    const int tx = threadIdx.x, ty = threadIdx.y;
    const int n0 = blockIdx.x * 32, k0 = blockIdx.y * 32;
    #pragma unroll
    for (int i = 0; i < 32; i += 8) {
        int k = k0 + ty + i, n = n0 + tx;
        ts[ty + i][tx] = (k < R && n < nlimit) ? W[(size_t)k * Cstride + n] : 0.f;
    }
    __syncthreads();
    #pragma unroll
    for (int i = 0; i < 32; i += 8) {
        int n = n0 + ty + i, k = k0 + tx;
        if (n < nlimit && k < R) {
            int np = n;
            if (compact) {
                int r6 = n % 6;
                if (r6 == 3) continue;
                np = (n / 6) * 5 + (r6 < 3 ? r6 : r6 - 1);
            }
            Thi[(size_t)np * ldt + k] = __float2half(ts[tx][ty + i]);
        }
    }
}

// ---------------- gather W3 tail cols + bias5 --------------------------------
__global__ __launch_bounds__(256)
void gather_tail(const float* __restrict__ W3, const float* __restrict__ b3,
                 float* __restrict__ w3t12, float* __restrict__ bias5)
{
    int i = blockIdx.x * 256 + threadIdx.x;
    if (i < CS * 12) {
        int c = i / 12, j = i % 12;
        w3t12[(size_t)j * CSP + c] = W3[(size_t)c * CS + MK + j];
    }
    if (i < MK5) {
        int m6 = i / 5, j5 = i - m6 * 5;
        int kk = (j5 < 3) ? j5 : j5 + 1;
        bias5[i] = b3[m6 * 6 + kk];
    }
}

// ---------------- z -> fp16 hi/lo (contiguous [B][128]) ---------------------
__global__ __launch_bounds__(256)
void zprep(const float* __restrict__ x, __half* __restrict__ zhi, __half* __restrict__ zlo)
{
    int i = blockIdx.x * 256 + threadIdx.x;
    if (i < B_SZ * LAT) {
        int b = i >> 7, c = i & 127;
        float v = x[(size_t)b * XCOLS + (IN_F + 1) + c];
        __half h = __float2half(v);
        zhi[i] = h;
        zlo[i] = __float2half(v - __half2float(h));
    }
}

// ---------------- tail GEMM: 32 rows/block, 8 thr/row, shfl reduce ----------
__global__ __launch_bounds__(256)
void tail_gemm(const __half* __restrict__ h2h,
               const float* __restrict__ w3t12,
               const float* __restrict__ b3,
               const float* __restrict__ x,
               float* __restrict__ v5)
{
    __shared__ __half h2s[32 * 72];
    __shared__ float  w3s[64 * 12];

    const int tid = threadIdx.x;
    const int bm = blockIdx.x * 32;
    const int row_l = tid >> 3;
    const int ksub = tid & 7;

    float acc[12];
    #pragma unroll
    for (int j = 0; j < 12; ++j) acc[j] = 0.f;

    for (int kc = 0; kc < NKCS; ++kc) {
        {
            uint4 v = *reinterpret_cast<const uint4*>(
                h2h + (size_t)(bm + row_l) * CSP + kc * 64 + ksub * 8);
            *reinterpret_cast<uint4*>(&h2s[row_l * 72 + ksub * 8]) = v;
        }
        for (int i = tid; i < 64 * 12; i += 256) {
            int k = i / 12, j = i % 12;
            w3s[i] = w3t12[(size_t)j * CSP + kc * 64 + k];
        }
        __syncthreads();

        #pragma unroll
        for (int kk = 0; kk < 8; ++kk) {
            int k = kk * 8 + ksub;
            float hv = __half2float(h2s[row_l * 72 + k]);
            #pragma unroll
            for (int j = 0; j < 12; ++j)
                acc[j] = fmaf(hv, w3s[k * 12 + j], acc[j]);
        }
        __syncthreads();
    }

    #pragma unroll
    for (int j = 0; j < 12; ++j) {
        #pragma unroll
        for (int d = 4; d > 0; d >>= 1)
            acc[j] += __shfl_down_sync(0xffffffffu, acc[j], d);
    }

    if (ksub == 0) {
        float s = x[(size_t)(B_SZ - 1) * XCOLS + IN_F];
        float dt[12];
        #pragma unroll
        for (int j = 0; j < 12; ++j) dt[j] = acc[j] + b3[MK + j];
        #pragma unroll
        for (int t5 = 0; t5 < 5; ++t5) {
            int k = (t5 < 3) ? t5 : t5 + 1;
            float sv = fmaf(s, dt[k], dt[k + 6]);
            float r = (k < 3) ? cosf(sv * (float)k) : sinf(sv * (float)(k - 3));
            v5[(size_t)(bm + row_l) * 5 + t5] = r;
        }
    }
}

// ---------------- final: out[b,o] = sum_i inp[b,i]*w[b,i*64+o] + w[b,1024+o] -
__global__ __launch_bounds__(256)
void final_kernel(const float* __restrict__ w,
                  const float* __restrict__ x,
                  float* __restrict__ out)
{
    __shared__ float inp[4][IN_F];
    const int tid = threadIdx.x;
    const int b0 = blockIdx.x * 4;
    if (tid < 4 * IN_F)
        inp[tid >> 4][tid & 15] = x[(size_t)(b0 + (tid >> 4)) * XCOLS + (tid & 15)];
    __syncthreads();

    const int r = tid >> 6;
    const int o = tid & 63;
    const int b = b0 + r;
    const float* wr = w + (size_t)b * NGRP;
    float accum = wr[1024 + o];
    #pragma unroll
    for (int i = 0; i < IN_F; ++i)
        accum = fmaf(inp[r][i], wr[i * 64 + o], accum);
    out[(size_t)b * 64 + o] = accum;
}

// ----------------------------- launch ---------------------------------------
extern "C" void kernel_launch(void* const* d_in, const int* in_sizes, int n_in,
                              void* d_out, int out_size)
{
    const float* x  = (const float*)d_in[0];
    const float* W1 = (const float*)d_in[1];
    const float* b1 = (const float*)d_in[2];
    const float* W2 = (const float*)d_in[3];
    const float* b2 = (const float*)d_in[4];
    const float* W3 = (const float*)d_in[5];
    const float* b3 = (const float*)d_in[6];
    float* out = (float*)d_out;

    __half *zhi, *zlo, *w1t, *h1h, *h2h, *w2th, *w3th;
    float *w3t12, *bias5, *wbuf, *v5;
    cudaGetSymbolAddress((void**)&zhi,  g_zhi);
    cudaGetSymbolAddress((void**)&zlo,  g_zlo);
    cudaGetSymbolAddress((void**)&w1t,  g_w1t);
    cudaGetSymbolAddress((void**)&h1h,  g_h1h);
    cudaGetSymbolAddress((void**)&h2h,  g_h2h);
    cudaGetSymbolAddress((void**)&w2th, g_w2th);
    cudaGetSymbolAddress((void**)&w3th, g_w3th);
    cudaGetSymbolAddress((void**)&w3t12, g_w3t12);
    cudaGetSymbolAddress((void**)&bias5, g_bias5);
    cudaGetSymbolAddress((void**)&wbuf, g_w);
    cudaGetSymbolAddress((void**)&v5,  g_v5);

    const int SM_2P = 3 * 384 * ROWB1;   // 165888
    const int SM_1P = 3 * 256 * ROWB1;   // 110592

    static bool attr_set = false;
    if (!attr_set) {
        cudaFuncSetAttribute(gemm_f16<1>, cudaFuncAttributeMaxDynamicSharedMemorySize, SM_2P);
        cudaFuncSetAttribute(gemm_f16<0>, cudaFuncAttributeMaxDynamicSharedMemorySize, SM_1P);
        cudaFuncSetAttribute(gemm_w, cudaFuncAttributeMaxDynamicSharedMemorySize, W_SMEM);
        attr_set = true;
    }

    // 0) prep
    transpose_h<<<dim3((CS + 31) / 32, (HID + 31) / 32), dim3(32, 8)>>>(
        W2, HID, CS, CS, w2th, HID, 0);
    transpose_h<<<dim3((MK + 31) / 32, (CS + 31) / 32), dim3(32, 8)>>>(
        W3, CS, CS, MK, w3th, CSP, 1);
    transpose_h<<<dim3((HID + 31) / 32, (LAT + 31) / 32), dim3(32, 8)>>>(
        W1, LAT, HID, HID, w1t, LAT, 0);
    gather_tail<<<(CS * 12 + 255) / 256, 256>>>(W3, b3, w3t12, bias5);
    zprep<<<(B_SZ * LAT + 255) / 256, 256>>>(x, zhi, zlo);

    // 1) h1 = tanh(z @ W1 + b1): 2-pass (exact z), K=128
    gemm_f16<1><<<dim3(HID / 128, B_SZ / 128), 256, SM_2P>>>(
        zhi, zlo, LAT, w1t, LAT, LAT / 64, b1, h1h, HID, HID);

    // 2) h2 = tanh(h1 @ W2 + b2): 1-pass, K=1024, HW-tanh epilogue
    gemm_f16<0><<<dim3(CSP / 128, B_SZ / 128), 256, SM_1P>>>(
        h1h, nullptr, HID, w2th, HID, HID / 64, b2, h2h, CSP, CS);

    // 3) tail mini-GEMM -> v5
    tail_gemm<<<B_SZ / 32, 256>>>(h2h, w3t12, b3, x, v5);

    // 4) big GEMM + fused group-of-5 reduction -> w[B][1088]
    gemm_w<<<dim3(MK5 / 160, B_SZ / 256), 512, W_SMEM>>>(
        h2h, w3th, bias5, v5, wbuf);

    // 5) adaptive 16->64 linear from fused weights
    final_kernel<<<B_SZ / 4, 256>>>(wbuf, x, out);
}

// round 15
// speedup vs baseline: 1.1381x; 1.0112x over previous
#include <cuda_runtime.h>
#include <cuda_fp16.h>
#include <math.h>
#include <stdint.h>

// ---------------- problem constants ----------------
#define B_SZ   8192
#define XCOLS  145
#define IN_F   16
#define LAT    128
#define HID    1024
#define CS     6540     // (M+2)*K
#define CSP    6656     // CS padded to 256
#define MK     6528     // M*K
#define MK5    5440     // compacted (drop k%6==3, v==0); = 34*160
#define NGRP   1088     // MK5/5
#define NKCS   103      // ceil(CS/64): K-chunks needed (pads zero)

// ---------------- scratch (zero-initialized device globals) -----------------
__device__ __half g_zhi [(size_t)B_SZ * LAT];
__device__ __half g_zlo [(size_t)B_SZ * LAT];
__device__ __half g_w1t [(size_t)HID * LAT];
__device__ __half g_h1h [(size_t)B_SZ * HID];
__device__ __half g_h2h [(size_t)B_SZ * CSP];     // pads stay zero
__device__ __half g_w2th[(size_t)CSP * HID];
__device__ __half g_w3th[(size_t)MK5 * CSP];      // compact, K-pads zero
__device__ float  g_w3t12[(size_t)12 * CSP];      // tail cols, pads zero
__device__ float  g_bias5[(size_t)MK5];           // expanded b3 per compact col
__device__ float  g_w   [(size_t)B_SZ * NGRP];    // fused weights
__device__ float  g_v5  [(size_t)B_SZ * 5];

// ---------------- low-level helpers ----------------
__device__ __forceinline__ uint32_t smem_u32(const void* p) {
    uint32_t a;
    asm("{ .reg .u64 t; cvta.to.shared.u64 t, %1; cvt.u32.u64 %0, t; }" : "=r"(a) : "l"(p));
    return a;
}
__device__ __forceinline__ void cpa16(uint32_t dst, const void* src) {
    asm volatile("cp.async.cg.shared.global [%0], [%1], 16;" :: "r"(dst), "l"(src));
}
#define CP_COMMIT() asm volatile("cp.async.commit_group;" ::: "memory")
#define CP_WAIT2()  asm volatile("cp.async.wait_group 2;" ::: "memory")
#define CP_WAIT0()  asm volatile("cp.async.wait_group 0;" ::: "memory")

__device__ __forceinline__ void ldsm4(uint32_t& r0, uint32_t& r1, uint32_t& r2, uint32_t& r3,
                                      uint32_t addr) {
    asm volatile("ldmatrix.sync.aligned.m8n8.x4.shared.b16 {%0,%1,%2,%3}, [%4];"
                 : "=r"(r0), "=r"(r1), "=r"(r2), "=r"(r3) : "r"(addr));
}
__device__ __forceinline__ void mma_f16(float* c, const uint32_t* a, uint32_t b0, uint32_t b1) {
    asm volatile(
        "mma.sync.aligned.m16n8k16.row.col.f32.f16.f16.f32 "
        "{%0,%1,%2,%3}, {%4,%5,%6,%7}, {%8,%9}, {%0,%1,%2,%3};"
        : "+f"(c[0]), "+f"(c[1]), "+f"(c[2]), "+f"(c[3])
        : "r"(a[0]), "r"(a[1]), "r"(a[2]), "r"(a[3]), "r"(b0), "r"(b1));
}
// HW tanh (MUFU.TANH, sm_75+)
__device__ __forceinline__ float tanh_hw(float x) {
    float y;
    asm("tanh.approx.f32 %0, %1;" : "=f"(y) : "f"(x));
    return y;
}

// ============================================================================
// GEMM (h1 / h2): fp16 HMMA f32-acc, tile 128x128, BK=64, 3 stages, 256 thr.
// TWOPASS: A = Ahi + Alo.  out fp16 = tanh_hw(acc + bias[col])
// ============================================================================
#define ROWB1 144

template<int TWOPASS>
__global__ __launch_bounds__(256, TWOPASS ? 1 : 2)
void gemm_f16(const __half* __restrict__ A, const __half* __restrict__ Alo, int lda,
              const __half* __restrict__ B, int ldb, int nk,
              const float* __restrict__ bias,
              __half* __restrict__ outp, int ldo, int Nlimit)
{
    constexpr int ALO_OFF = 128 * ROWB1;
    constexpr int B_OFF   = (TWOPASS ? 256 : 128) * ROWB1;
    constexpr int STG     = (TWOPASS ? 384 : 256) * ROWB1;

    extern __shared__ char smem[];
    const uint32_t sbase = smem_u32(smem);
    const int tid  = threadIdx.x;
    const int lane = tid & 31;
    const int wid  = tid >> 5;
    const int warp_m = wid & 3;
    const int warp_n = wid >> 2;
    const int bm = blockIdx.y * 128;
    const int bn = blockIdx.x * 128;

    const int lrow = tid >> 1;
    const int lhalf = tid & 1;
    const char* aSrc  = (const char*)(A + (size_t)(bm + lrow) * lda) + lhalf * 64;
    const char* alSrc = (const char*)(Alo + (size_t)(bm + lrow) * lda) + lhalf * 64;
    const char* bSrc  = (const char*)(B + (size_t)(bn + lrow) * ldb) + lhalf * 64;
    const uint32_t dA = lrow * ROWB1 + lhalf * 64;

    float acc[2][8][4];
    #pragma unroll
    for (int i = 0; i < 2; ++i)
        #pragma unroll
        for (int j = 0; j < 8; ++j)
            #pragma unroll
            for (int l = 0; l < 4; ++l) acc[i][j][l] = 0.f;

    auto load_stage = [&](int s, int kc) {
        const uint32_t sA = sbase + s * STG;
        const size_t kb = (size_t)kc * 128;
        #pragma unroll
        for (int j = 0; j < 4; ++j) {
            cpa16(sA + dA + j * 16,         aSrc + kb + j * 16);
            if (TWOPASS) cpa16(sA + ALO_OFF + dA + j * 16, alSrc + kb + j * 16);
            cpa16(sA + B_OFF + dA + j * 16, bSrc + kb + j * 16);
        }
    };

    load_stage(0, 0); CP_COMMIT();
    if (nk > 1) load_stage(1, 1);
    CP_COMMIT();

    const int l15  = lane & 15;
    const int lksl = (lane >> 4) & 1;

    for (int k = 0; k < nk; ++k) {
        const int fetch = k + 2;
        if (fetch < nk) load_stage(fetch % 3, fetch);
        CP_COMMIT();
        CP_WAIT2();
        __syncthreads();

        const uint32_t sA = sbase + (k % 3) * STG;
        const uint32_t sB = sA + B_OFF;

        #pragma unroll
        for (int ks = 0; ks < 4; ++ks) {
            const uint32_t koff = ks * 32 + lksl * 16;
            uint32_t a[2][4], al[2][4];
            #pragma unroll
            for (int mt = 0; mt < 2; ++mt) {
                uint32_t ra = sA + (uint32_t)(warp_m * 32 + mt * 16 + l15) * ROWB1 + koff;
                ldsm4(a[mt][0], a[mt][1], a[mt][2], a[mt][3], ra);
                if (TWOPASS)
                    ldsm4(al[mt][0], al[mt][1], al[mt][2], al[mt][3], ra + ALO_OFF);
            }
            uint32_t bh[2][4];
            {
                uint32_t rb = sB + (uint32_t)(warp_n * 64 + l15) * ROWB1 + koff;
                ldsm4(bh[0][0], bh[0][1], bh[0][2], bh[0][3], rb);
            }
            #pragma unroll
            for (int g = 0; g < 4; ++g) {
                const int cur = g & 1, nxt = cur ^ 1;
                if (g < 3) {
                    uint32_t rb = sB + (uint32_t)(warp_n * 64 + (g + 1) * 16 + l15) * ROWB1 + koff;
                    ldsm4(bh[nxt][0], bh[nxt][1], bh[nxt][2], bh[nxt][3], rb);
                }
                float* c00 = acc[0][2 * g];
                float* c01 = acc[0][2 * g + 1];
                float* c10 = acc[1][2 * g];
                float* c11 = acc[1][2 * g + 1];
                mma_f16(c00, a[0], bh[cur][0], bh[cur][2]);
                mma_f16(c01, a[0], bh[cur][1], bh[cur][3]);
                mma_f16(c10, a[1], bh[cur][0], bh[cur][2]);
                mma_f16(c11, a[1], bh[cur][1], bh[cur][3]);
                if (TWOPASS) {
                    mma_f16(c00, al[0], bh[cur][0], bh[cur][2]);
                    mma_f16(c01, al[0], bh[cur][1], bh[cur][3]);
                    mma_f16(c10, al[1], bh[cur][0], bh[cur][2]);
                    mma_f16(c11, al[1], bh[cur][1], bh[cur][3]);
                }
            }
        }
        __syncthreads();
    }

    #pragma unroll
    for (int mt = 0; mt < 2; ++mt) {
        #pragma unroll
        for (int h = 0; h < 2; ++h) {
            const int row = bm + warp_m * 32 + mt * 16 + (lane >> 2) + h * 8;
            #pragma unroll
            for (int nt = 0; nt < 8; ++nt) {
                const int col = bn + warp_n * 64 + nt * 8 + ((lane & 3) << 1);
                if (col < Nlimit) {
                    float t0 = tanh_hw(acc[mt][nt][h * 2 + 0] + bias[col]);
                    float t1 = tanh_hw(acc[mt][nt][h * 2 + 1] + bias[col + 1]);
                    __half2 hp;
                    hp.x = __float2half(t0);
                    hp.y = __float2half(t1);
                    *reinterpret_cast<__half2*>(outp + (size_t)row * ldo + col) = hp;
                }
            }
        }
    }
}

// ============================================================================
// Big GEMM + fused group-of-5 reduction: tile 256x160, BK=64, 3 stages, 512thr.
// Main loop runs NKCS-1 full chunks; the final chunk is peeled and runs only
// its first k16 step (covers k in [6528,6544) >= CS; the other 3 steps would
// multiply guaranteed-zero pads on both operands).
// ============================================================================
#define W_BOFF (256 * ROWB1)            // 36864
#define W_STG  ((256 + 160) * ROWB1)    // 59904
#define W_SMEM (3 * W_STG)              // 179712
#define W_PADN 164

__global__ __launch_bounds__(512, 1)
void gemm_w(const __half* __restrict__ A, const __half* __restrict__ B,
            const float* __restrict__ bias5, const float* __restrict__ v5,
            float* __restrict__ w)
{
    extern __shared__ char smem[];
    const uint32_t sbase = smem_u32(smem);
    const int tid  = threadIdx.x;
    const int lane = tid & 31;
    const int wid  = tid >> 5;
    const int warp_m = wid & 7;           // 0..7 (32 rows each)
    const int warp_n = wid >> 3;          // 0..1 (80 cols each)
    const int bm = blockIdx.y * 256;
    const int bn = blockIdx.x * 160;

    const bool isA = tid < 256;
    const int ltid = isA ? tid : tid - 256;
    const int lrow = ltid >> 3;
    const int lcol = ltid & 7;
    const char* gsrc = isA
        ? (const char*)(A + (size_t)(bm + lrow) * CSP) + lcol * 16
        : (const char*)(B + (size_t)(bn + lrow) * CSP) + lcol * 16;
    const uint32_t dst0 = (isA ? 0u : (uint32_t)W_BOFF) + lrow * ROWB1 + lcol * 16;
    const size_t gstr = (size_t)32 * CSP * 2;

    float acc[2][10][4];
    #pragma unroll
    for (int i = 0; i < 2; ++i)
        #pragma unroll
        for (int j = 0; j < 10; ++j)
            #pragma unroll
            for (int l = 0; l < 4; ++l) acc[i][j][l] = 0.f;

    auto load_stage = [&](int s, int kc) {
        const uint32_t base = sbase + s * W_STG + dst0;
        const char* g = gsrc + (size_t)kc * 128;
        if (isA) {
            #pragma unroll
            for (int t = 0; t < 8; ++t)
                cpa16(base + t * (32 * ROWB1), g + t * gstr);
        } else {
            #pragma unroll
            for (int t = 0; t < 5; ++t)
                cpa16(base + t * (32 * ROWB1), g + t * gstr);
        }
    };

    const int nk = NKCS;   // 103
    load_stage(0, 0); CP_COMMIT();
    load_stage(1, 1); CP_COMMIT();

    const int l15  = lane & 15;
    const int lksl = (lane >> 4) & 1;

    // main loop: full BK=64 chunks 0 .. nk-2
    for (int k = 0; k < nk - 1; ++k) {
        const int fetch = k + 2;
        if (fetch < nk) load_stage(fetch % 3, fetch);
        CP_COMMIT();
        CP_WAIT2();
        __syncthreads();

        const uint32_t sA = sbase + (k % 3) * W_STG;
        const uint32_t sB = sA + W_BOFF;

        #pragma unroll
        for (int ks = 0; ks < 4; ++ks) {
            const uint32_t koff = ks * 32 + lksl * 16;
            uint32_t a[2][4];
            #pragma unroll
            for (int mt = 0; mt < 2; ++mt) {
                uint32_t ra = sA + (uint32_t)(warp_m * 32 + mt * 16 + l15) * ROWB1 + koff;
                ldsm4(a[mt][0], a[mt][1], a[mt][2], a[mt][3], ra);
            }
            uint32_t bh[2][4];
            {
                uint32_t rb = sB + (uint32_t)(warp_n * 80 + l15) * ROWB1 + koff;
                ldsm4(bh[0][0], bh[0][1], bh[0][2], bh[0][3], rb);
            }
            #pragma unroll
            for (int g = 0; g < 5; ++g) {
                const int cur = g & 1, nxt = cur ^ 1;
                if (g < 4) {
                    uint32_t rb = sB + (uint32_t)(warp_n * 80 + (g + 1) * 16 + l15) * ROWB1 + koff;
                    ldsm4(bh[nxt][0], bh[nxt][1], bh[nxt][2], bh[nxt][3], rb);
                }
                mma_f16(acc[0][2 * g],     a[0], bh[cur][0], bh[cur][2]);
                mma_f16(acc[0][2 * g + 1], a[0], bh[cur][1], bh[cur][3]);
                mma_f16(acc[1][2 * g],     a[1], bh[cur][0], bh[cur][2]);
                mma_f16(acc[1][2 * g + 1], a[1], bh[cur][1], bh[cur][3]);
            }
        }
        __syncthreads();
    }

    // peeled last chunk: only ks=0 (k in [6528,6544) covers CS; rest is zero pad)
    {
        CP_WAIT0();
        __syncthreads();
        const uint32_t sA = sbase + ((nk - 1) % 3) * W_STG;
        const uint32_t sB = sA + W_BOFF;
        const uint32_t koff = lksl * 16;
        uint32_t a[2][4];
        #pragma unroll
        for (int mt = 0; mt < 2; ++mt) {
            uint32_t ra = sA + (uint32_t)(warp_m * 32 + mt * 16 + l15) * ROWB1 + koff;
            ldsm4(a[mt][0], a[mt][1], a[mt][2], a[mt][3], ra);
        }
        uint32_t bh[2][4];
        {
            uint32_t rb = sB + (uint32_t)(warp_n * 80 + l15) * ROWB1 + koff;
            ldsm4(bh[0][0], bh[0][1], bh[0][2], bh[0][3], rb);
        }
        #pragma unroll
        for (int g = 0; g < 5; ++g) {
            const int cur = g & 1, nxt = cur ^ 1;
            if (g < 4) {
                uint32_t rb = sB + (uint32_t)(warp_n * 80 + (g + 1) * 16 + l15) * ROWB1 + koff;
                ldsm4(bh[nxt][0], bh[nxt][1], bh[nxt][2], bh[nxt][3], rb);
            }
            mma_f16(acc[0][2 * g],     a[0], bh[cur][0], bh[cur][2]);
            mma_f16(acc[0][2 * g + 1], a[0], bh[cur][1], bh[cur][3]);
            mma_f16(acc[1][2 * g],     a[1], bh[cur][0], bh[cur][2]);
            mma_f16(acc[1][2 * g + 1], a[1], bh[cur][1], bh[cur][3]);
        }
        __syncthreads();
    }

    // ---------------- fused epilogue: stage tile, reduce groups of 5 --------
    float* stg = reinterpret_cast<float*>(smem);          // [256][164]
    float* v5s = stg + 256 * W_PADN;                       // [256][5]
    float* b5s = v5s + 256 * 5;                            // [160]

    #pragma unroll
    for (int mt = 0; mt < 2; ++mt) {
        #pragma unroll
        for (int h = 0; h < 2; ++h) {
            const int row = warp_m * 32 + mt * 16 + (lane >> 2) + h * 8;
            #pragma unroll
            for (int nt = 0; nt < 10; ++nt) {
                const int col = warp_n * 80 + nt * 8 + ((lane & 3) << 1);
                stg[row * W_PADN + col]     = acc[mt][nt][h * 2 + 0];
                stg[row * W_PADN + col + 1] = acc[mt][nt][h * 2 + 1];
            }
        }
    }
    for (int i = tid; i < 256 * 5; i += 512) v5s[i] = v5[(size_t)bm * 5 + i];
    if (tid < 160) b5s[tid] = bias5[bn + tid];
    __syncthreads();

    const int gbase = blockIdx.x * 32;
    for (int i = tid; i < 256 * 32; i += 512) {
        const int row = i >> 5, grp = i & 31;
        const float* p  = stg + row * W_PADN + grp * 5;
        const float* vv = v5s + row * 5;
        const float* bb = b5s + grp * 5;
        float s = (p[0] + bb[0]) * vv[0];
        s = fmaf(p[1] + bb[1], vv[1], s);
        s = fmaf(p[2] + bb[2], vv[2], s);
        s = fmaf(p[3] + bb[3], vv[3], s);
        s = fmaf(p[4] + bb[4], vv[4], s);
        w[(size_t)(bm + row) * NGRP + gbase + grp] = s;
    }
}

// ---------------- transpose + fp16 (optionally compact k%6==3) --------------
__global__ __launch_bounds__(256)
void transpose_h(const float* __restrict__ W, int R, int Cstride, int nlimit,
                 __half* __restrict__ Thi, int ldt, int compact)
{
    __shared__ float ts[32][33];
    const int tx = threadIdx.x, ty = threadIdx.y;
    const int n0 = blockIdx.x * 32, k0 = blockIdx.y * 32;
    #pragma unroll
    for (int i = 0; i < 32; i += 8) {
        int k = k0 + ty + i, n = n0 + tx;
        ts[ty + i][tx] = (k < R && n < nlimit) ? W[(size_t)k * Cstride + n] : 0.f;
    }
    __syncthreads();
    #pragma unroll
    for (int i = 0; i < 32; i += 8) {
        int n = n0 + ty + i, k = k0 + tx;
        if (n < nlimit && k < R) {
            int np = n;
            if (compact) {
                int r6 = n % 6;
                if (r6 == 3) continue;
                np = (n / 6) * 5 + (r6 < 3 ? r6 : r6 - 1);
            }
            Thi[(size_t)np * ldt + k] = __float2half(ts[tx][ty + i]);
        }
    }
}

// ---------------- gather W3 tail cols + bias5 --------------------------------
__global__ __launch_bounds__(256)
void gather_tail(const float* __restrict__ W3, const float* __restrict__ b3,
                 float* __restrict__ w3t12, float* __restrict__ bias5)
{
    int i = blockIdx.x * 256 + threadIdx.x;
    if (i < CS * 12) {
        int c = i / 12, j = i % 12;
        w3t12[(size_t)j * CSP + c] = W3[(size_t)c * CS + MK + j];
    }
    if (i < MK5) {
        int m6 = i / 5, j5 = i - m6 * 5;
        int kk = (j5 < 3) ? j5 : j5 + 1;
        bias5[i] = b3[m6 * 6 + kk];
    }
}

// ---------------- z -> fp16 hi/lo (contiguous [B][128]) ---------------------
__global__ __launch_bounds__(256)
void zprep(const float* __restrict__ x, __half* __restrict__ zhi, __half* __restrict__ zlo)
{
    int i = blockIdx.x * 256 + threadIdx.x;
    if (i < B_SZ * LAT) {
        int b = i >> 7, c = i & 127;
        float v = x[(size_t)b * XCOLS + (IN_F + 1) + c];
        __half h = __float2half(v);
        zhi[i] = h;
        zlo[i] = __float2half(v - __half2float(h));
    }
}

// ---------------- tail GEMM: 32 rows/block, 8 thr/row, shfl reduce ----------
__global__ __launch_bounds__(256)
void tail_gemm(const __half* __restrict__ h2h,
               const float* __restrict__ w3t12,
               const float* __restrict__ b3,
               const float* __restrict__ x,
               float* __restrict__ v5)
{
    __shared__ __half h2s[32 * 72];
    __shared__ float  w3s[64 * 12];

    const int tid = threadIdx.x;
    const int bm = blockIdx.x * 32;
    const int row_l = tid >> 3;
    const int ksub = tid & 7;

    float acc[12];
    #pragma unroll
    for (int j = 0; j < 12; ++j) acc[j] = 0.f;

    for (int kc = 0; kc < NKCS; ++kc) {
        {
            uint4 v = *reinterpret_cast<const uint4*>(
                h2h + (size_t)(bm + row_l) * CSP + kc * 64 + ksub * 8);
            *reinterpret_cast<uint4*>(&h2s[row_l * 72 + ksub * 8]) = v;
        }
        for (int i = tid; i < 64 * 12; i += 256) {
            int k = i / 12, j = i % 12;
            w3s[i] = w3t12[(size_t)j * CSP + kc * 64 + k];
        }
        __syncthreads();

        #pragma unroll
        for (int kk = 0; kk < 8; ++kk) {
            int k = kk * 8 + ksub;
            float hv = __half2float(h2s[row_l * 72 + k]);
            #pragma unroll
            for (int j = 0; j < 12; ++j)
                acc[j] = fmaf(hv, w3s[k * 12 + j], acc[j]);
        }
        __syncthreads();
    }

    #pragma unroll
    for (int j = 0; j < 12; ++j) {
        #pragma unroll
        for (int d = 4; d > 0; d >>= 1)
            acc[j] += __shfl_down_sync(0xffffffffu, acc[j], d);
    }

    if (ksub == 0) {
        float s = x[(size_t)(B_SZ - 1) * XCOLS + IN_F];
        float dt[12];
        #pragma unroll
        for (int j = 0; j < 12; ++j) dt[j] = acc[j] + b3[MK + j];
        #pragma unroll
        for (int t5 = 0; t5 < 5; ++t5) {
            int k = (t5 < 3) ? t5 : t5 + 1;
            float sv = fmaf(s, dt[k], dt[k + 6]);
            float r = (k < 3) ? cosf(sv * (float)k) : sinf(sv * (float)(k - 3));
            v5[(size_t)(bm + row_l) * 5 + t5] = r;
        }
    }
}

// ---------------- final: out[b,o] = sum_i inp[b,i]*w[b,i*64+o] + w[b,1024+o] -
__global__ __launch_bounds__(256)
void final_kernel(const float* __restrict__ w,
                  const float* __restrict__ x,
                  float* __restrict__ out)
{
    __shared__ float inp[4][IN_F];
    const int tid = threadIdx.x;
    const int b0 = blockIdx.x * 4;
    if (tid < 4 * IN_F)
        inp[tid >> 4][tid & 15] = x[(size_t)(b0 + (tid >> 4)) * XCOLS + (tid & 15)];
    __syncthreads();

    const int r = tid >> 6;
    const int o = tid & 63;
    const int b = b0 + r;
    const float* wr = w + (size_t)b * NGRP;
    float accum = wr[1024 + o];
    #pragma unroll
    for (int i = 0; i < IN_F; ++i)
        accum = fmaf(inp[r][i], wr[i * 64 + o], accum);
    out[(size_t)b * 64 + o] = accum;
}

// ----------------------------- launch ---------------------------------------
extern "C" void kernel_launch(void* const* d_in, const int* in_sizes, int n_in,
                              void* d_out, int out_size)
{
    const float* x  = (const float*)d_in[0];
    const float* W1 = (const float*)d_in[1];
    const float* b1 = (const float*)d_in[2];
    const float* W2 = (const float*)d_in[3];
    const float* b2 = (const float*)d_in[4];
    const float* W3 = (const float*)d_in[5];
    const float* b3 = (const float*)d_in[6];
    float* out = (float*)d_out;

    __half *zhi, *zlo, *w1t, *h1h, *h2h, *w2th, *w3th;
    float *w3t12, *bias5, *wbuf, *v5;
    cudaGetSymbolAddress((void**)&zhi,  g_zhi);
    cudaGetSymbolAddress((void**)&zlo,  g_zlo);
    cudaGetSymbolAddress((void**)&w1t,  g_w1t);
    cudaGetSymbolAddress((void**)&h1h,  g_h1h);
    cudaGetSymbolAddress((void**)&h2h,  g_h2h);
    cudaGetSymbolAddress((void**)&w2th, g_w2th);
    cudaGetSymbolAddress((void**)&w3th, g_w3th);
    cudaGetSymbolAddress((void**)&w3t12, g_w3t12);
    cudaGetSymbolAddress((void**)&bias5, g_bias5);
    cudaGetSymbolAddress((void**)&wbuf, g_w);
    cudaGetSymbolAddress((void**)&v5,  g_v5);

    const int SM_2P = 3 * 384 * ROWB1;   // 165888
    const int SM_1P = 3 * 256 * ROWB1;   // 110592

    static bool attr_set = false;
    if (!attr_set) {
        cudaFuncSetAttribute(gemm_f16<1>, cudaFuncAttributeMaxDynamicSharedMemorySize, SM_2P);
        cudaFuncSetAttribute(gemm_f16<0>, cudaFuncAttributeMaxDynamicSharedMemorySize, SM_1P);
        cudaFuncSetAttribute(gemm_w, cudaFuncAttributeMaxDynamicSharedMemorySize, W_SMEM);
        attr_set = true;
    }

    // 0) prep
    transpose_h<<<dim3((CS + 31) / 32, (HID + 31) / 32), dim3(32, 8)>>>(
        W2, HID, CS, CS, w2th, HID, 0);
    transpose_h<<<dim3((MK + 31) / 32, (CS + 31) / 32), dim3(32, 8)>>>(
        W3, CS, CS, MK, w3th, CSP, 1);
    transpose_h<<<dim3((HID + 31) / 32, (LAT + 31) / 32), dim3(32, 8)>>>(
        W1, LAT, HID, HID, w1t, LAT, 0);
    gather_tail<<<(CS * 12 + 255) / 256, 256>>>(W3, b3, w3t12, bias5);
    zprep<<<(B_SZ * LAT + 255) / 256, 256>>>(x, zhi, zlo);

    // 1) h1 = tanh(z @ W1 + b1): 2-pass (exact z), K=128
    gemm_f16<1><<<dim3(HID / 128, B_SZ / 128), 256, SM_2P>>>(
        zhi, zlo, LAT, w1t, LAT, LAT / 64, b1, h1h, HID, HID);

    // 2) h2 = tanh(h1 @ W2 + b2): 1-pass, K=1024, HW-tanh epilogue
    gemm_f16<0><<<dim3(CSP / 128, B_SZ / 128), 256, SM_1P>>>(
        h1h, nullptr, HID, w2th, HID, HID / 64, b2, h2h, CSP, CS);

    // 3) tail mini-GEMM -> v5
    tail_gemm<<<B_SZ / 32, 256>>>(h2h, w3t12, b3, x, v5);

    // 4) big GEMM (peeled last chunk) + fused group-of-5 reduction -> w
    gemm_w<<<dim3(MK5 / 160, B_SZ / 256), 512, W_SMEM>>>(
        h2h, w3th, bias5, v5, wbuf);

    // 5) adaptive 16->64 linear from fused weights
    final_kernel<<<B_SZ / 4, 256>>>(wbuf, x, out);
}

// round 16
// speedup vs baseline: 1.1600x; 1.0192x over previous
#include <cuda_runtime.h>
#include <cuda_fp16.h>
#include <math.h>
#include <stdint.h>

// ---------------- problem constants ----------------
#define B_SZ   8192
#define XCOLS  145
#define IN_F   16
#define LAT    128
#define HID    1024
#define CS     6540     // (M+2)*K
#define CSP    6656     // CS padded to 256
#define MK     6528     // M*K
#define MK5    5440     // compacted (drop k%6==3, v==0); = 34*160
#define NGRP   1088     // MK5/5
#define NKCS   103      // ceil(CS/64)
#define MFULL  28       // full 256-row M tiles
#define MBASE_HALF (MFULL * 256)   // 7168; remaining 1024 rows as 8 half tiles

// ---------------- scratch (zero-initialized device globals) -----------------
__device__ __half g_zhi [(size_t)B_SZ * LAT];
__device__ __half g_zlo [(size_t)B_SZ * LAT];
__device__ __half g_w1t [(size_t)HID * LAT];
__device__ __half g_h1h [(size_t)B_SZ * HID];
__device__ __half g_h2h [(size_t)B_SZ * CSP];     // pads stay zero
__device__ __half g_w2th[(size_t)CSP * HID];
__device__ __half g_w3th[(size_t)MK5 * CSP];      // compact, K-pads zero
__device__ float  g_w3t12[(size_t)12 * CSP];      // tail cols, pads zero
__device__ float  g_bias5[(size_t)MK5];           // expanded b3 per compact col
__device__ float  g_w   [(size_t)B_SZ * NGRP];    // fused weights
__device__ float  g_v5  [(size_t)B_SZ * 5];

// ---------------- low-level helpers ----------------
__device__ __forceinline__ uint32_t smem_u32(const void* p) {
    uint32_t a;
    asm("{ .reg .u64 t; cvta.to.shared.u64 t, %1; cvt.u32.u64 %0, t; }" : "=r"(a) : "l"(p));
    return a;
}
__device__ __forceinline__ void cpa16(uint32_t dst, const void* src) {
    asm volatile("cp.async.cg.shared.global [%0], [%1], 16;" :: "r"(dst), "l"(src));
}
#define CP_COMMIT() asm volatile("cp.async.commit_group;" ::: "memory")
#define CP_WAIT2()  asm volatile("cp.async.wait_group 2;" ::: "memory")
#define CP_WAIT0()  asm volatile("cp.async.wait_group 0;" ::: "memory")

__device__ __forceinline__ void ldsm4(uint32_t& r0, uint32_t& r1, uint32_t& r2, uint32_t& r3,
                                      uint32_t addr) {
    asm volatile("ldmatrix.sync.aligned.m8n8.x4.shared.b16 {%0,%1,%2,%3}, [%4];"
                 : "=r"(r0), "=r"(r1), "=r"(r2), "=r"(r3) : "r"(addr));
}
__device__ __forceinline__ void mma_f16(float* c, const uint32_t* a, uint32_t b0, uint32_t b1) {
    asm volatile(
        "mma.sync.aligned.m16n8k16.row.col.f32.f16.f16.f32 "
        "{%0,%1,%2,%3}, {%4,%5,%6,%7}, {%8,%9}, {%0,%1,%2,%3};"
        : "+f"(c[0]), "+f"(c[1]), "+f"(c[2]), "+f"(c[3])
        : "r"(a[0]), "r"(a[1]), "r"(a[2]), "r"(a[3]), "r"(b0), "r"(b1));
}
__device__ __forceinline__ float tanh_hw(float x) {
    float y;
    asm("tanh.approx.f32 %0, %1;" : "=f"(y) : "f"(x));
    return y;
}

// ============================================================================
// GEMM (h1 / h2): fp16 HMMA f32-acc, tile 128x128, BK=64, 3 stages, 256 thr.
// ============================================================================
#define ROWB1 144

template<int TWOPASS>
__global__ __launch_bounds__(256, TWOPASS ? 1 : 2)
void gemm_f16(const __half* __restrict__ A, const __half* __restrict__ Alo, int lda,
              const __half* __restrict__ B, int ldb, int nk,
              const float* __restrict__ bias,
              __half* __restrict__ outp, int ldo, int Nlimit)
{
    constexpr int ALO_OFF = 128 * ROWB1;
    constexpr int B_OFF   = (TWOPASS ? 256 : 128) * ROWB1;
    constexpr int STG     = (TWOPASS ? 384 : 256) * ROWB1;

    extern __shared__ char smem[];
    const uint32_t sbase = smem_u32(smem);
    const int tid  = threadIdx.x;
    const int lane = tid & 31;
    const int wid  = tid >> 5;
    const int warp_m = wid & 3;
    const int warp_n = wid >> 2;
    const int bm = blockIdx.y * 128;
    const int bn = blockIdx.x * 128;

    const int lrow = tid >> 1;
    const int lhalf = tid & 1;
    const char* aSrc  = (const char*)(A + (size_t)(bm + lrow) * lda) + lhalf * 64;
    const char* alSrc = (const char*)(Alo + (size_t)(bm + lrow) * lda) + lhalf * 64;
    const char* bSrc  = (const char*)(B + (size_t)(bn + lrow) * ldb) + lhalf * 64;
    const uint32_t dA = lrow * ROWB1 + lhalf * 64;

    float acc[2][8][4];
    #pragma unroll
    for (int i = 0; i < 2; ++i)
        #pragma unroll
        for (int j = 0; j < 8; ++j)
            #pragma unroll
            for (int l = 0; l < 4; ++l) acc[i][j][l] = 0.f;

    auto load_stage = [&](int s, int kc) {
        const uint32_t sA = sbase + s * STG;
        const size_t kb = (size_t)kc * 128;
        #pragma unroll
        for (int j = 0; j < 4; ++j) {
            cpa16(sA + dA + j * 16,         aSrc + kb + j * 16);
            if (TWOPASS) cpa16(sA + ALO_OFF + dA + j * 16, alSrc + kb + j * 16);
            cpa16(sA + B_OFF + dA + j * 16, bSrc + kb + j * 16);
        }
    };

    load_stage(0, 0); CP_COMMIT();
    if (nk > 1) load_stage(1, 1);
    CP_COMMIT();

    const int l15  = lane & 15;
    const int lksl = (lane >> 4) & 1;

    for (int k = 0; k < nk; ++k) {
        const int fetch = k + 2;
        if (fetch < nk) load_stage(fetch % 3, fetch);
        CP_COMMIT();
        CP_WAIT2();
        __syncthreads();

        const uint32_t sA = sbase + (k % 3) * STG;
        const uint32_t sB = sA + B_OFF;

        #pragma unroll
        for (int ks = 0; ks < 4; ++ks) {
            const uint32_t koff = ks * 32 + lksl * 16;
            uint32_t a[2][4], al[2][4];
            #pragma unroll
            for (int mt = 0; mt < 2; ++mt) {
                uint32_t ra = sA + (uint32_t)(warp_m * 32 + mt * 16 + l15) * ROWB1 + koff;
                ldsm4(a[mt][0], a[mt][1], a[mt][2], a[mt][3], ra);
                if (TWOPASS)
                    ldsm4(al[mt][0], al[mt][1], al[mt][2], al[mt][3], ra + ALO_OFF);
            }
            uint32_t bh[2][4];
            {
                uint32_t rb = sB + (uint32_t)(warp_n * 64 + l15) * ROWB1 + koff;
                ldsm4(bh[0][0], bh[0][1], bh[0][2], bh[0][3], rb);
            }
            #pragma unroll
            for (int g = 0; g < 4; ++g) {
                const int cur = g & 1, nxt = cur ^ 1;
                if (g < 3) {
                    uint32_t rb = sB + (uint32_t)(warp_n * 64 + (g + 1) * 16 + l15) * ROWB1 + koff;
                    ldsm4(bh[nxt][0], bh[nxt][1], bh[nxt][2], bh[nxt][3], rb);
                }
                float* c00 = acc[0][2 * g];
                float* c01 = acc[0][2 * g + 1];
                float* c10 = acc[1][2 * g];
                float* c11 = acc[1][2 * g + 1];
                mma_f16(c00, a[0], bh[cur][0], bh[cur][2]);
                mma_f16(c01, a[0], bh[cur][1], bh[cur][3]);
                mma_f16(c10, a[1], bh[cur][0], bh[cur][2]);
                mma_f16(c11, a[1], bh[cur][1], bh[cur][3]);
                if (TWOPASS) {
                    mma_f16(c00, al[0], bh[cur][0], bh[cur][2]);
                    mma_f16(c01, al[0], bh[cur][1], bh[cur][3]);
                    mma_f16(c10, al[1], bh[cur][0], bh[cur][2]);
                    mma_f16(c11, al[1], bh[cur][1], bh[cur][3]);
                }
            }
        }
        __syncthreads();
    }

    #pragma unroll
    for (int mt = 0; mt < 2; ++mt) {
        #pragma unroll
        for (int h = 0; h < 2; ++h) {
            const int row = bm + warp_m * 32 + mt * 16 + (lane >> 2) + h * 8;
            #pragma unroll
            for (int nt = 0; nt < 8; ++nt) {
                const int col = bn + warp_n * 64 + nt * 8 + ((lane & 3) << 1);
                if (col < Nlimit) {
                    float t0 = tanh_hw(acc[mt][nt][h * 2 + 0] + bias[col]);
                    float t1 = tanh_hw(acc[mt][nt][h * 2 + 1] + bias[col + 1]);
                    __half2 hp;
                    hp.x = __float2half(t0);
                    hp.y = __float2half(t1);
                    *reinterpret_cast<__half2*>(outp + (size_t)row * ldo + col) = hp;
                }
            }
        }
    }
}

// ============================================================================
// Big GEMM + fused group-of-5 reduction. Templated on MT (rows = 128*MT).
// MT=2: 256x160 tiles (steady state).  MT=1: 128x160 tiles (fine-grain drain).
// Last K chunk peeled: only its first k16 step carries data.
// ============================================================================
template<int MT>
__global__ __launch_bounds__(512, 1)
void gemm_w(const __half* __restrict__ A, const __half* __restrict__ B,
            const float* __restrict__ bias5, const float* __restrict__ v5,
            float* __restrict__ w, int mbase)
{
    constexpr int ROWS   = 128 * MT;
    constexpr int W_BOFF = ROWS * ROWB1;
    constexpr int W_STG  = (ROWS + 160) * ROWB1;
    constexpr int W_PADN = 164;

    extern __shared__ char smem[];
    const uint32_t sbase = smem_u32(smem);
    const int tid  = threadIdx.x;
    const int lane = tid & 31;
    const int wid  = tid >> 5;
    const int warp_m = wid & 7;           // 8 groups of (16*MT) rows
    const int warp_n = wid >> 3;          // 0..1 (80 cols each)
    const int bm = mbase + blockIdx.y * ROWS;
    const int bn = blockIdx.x * 160;

    const bool isA = tid < 256;
    const int ltid = isA ? tid : tid - 256;
    const int lrow = ltid >> 3;
    const int lcol = ltid & 7;
    const char* gsrc = isA
        ? (const char*)(A + (size_t)(bm + lrow) * CSP) + lcol * 16
        : (const char*)(B + (size_t)(bn + lrow) * CSP) + lcol * 16;
    const uint32_t dst0 = (isA ? 0u : (uint32_t)W_BOFF) + lrow * ROWB1 + lcol * 16;
    const size_t gstr = (size_t)32 * CSP * 2;

    float acc[MT][10][4];
    #pragma unroll
    for (int i = 0; i < MT; ++i)
        #pragma unroll
        for (int j = 0; j < 10; ++j)
            #pragma unroll
            for (int l = 0; l < 4; ++l) acc[i][j][l] = 0.f;

    auto load_stage = [&](int s, int kc) {
        const uint32_t base = sbase + s * W_STG + dst0;
        const char* g = gsrc + (size_t)kc * 128;
        if (isA) {
            #pragma unroll
            for (int t = 0; t < 4 * MT; ++t)
                cpa16(base + t * (32 * ROWB1), g + t * gstr);
        } else {
            #pragma unroll
            for (int t = 0; t < 5; ++t)
                cpa16(base + t * (32 * ROWB1), g + t * gstr);
        }
    };

    const int nk = NKCS;   // 103
    load_stage(0, 0); CP_COMMIT();
    load_stage(1, 1); CP_COMMIT();

    const int l15  = lane & 15;
    const int lksl = (lane >> 4) & 1;

    for (int k = 0; k < nk - 1; ++k) {
        const int fetch = k + 2;
        if (fetch < nk) load_stage(fetch % 3, fetch);
        CP_COMMIT();
        CP_WAIT2();
        __syncthreads();

        const uint32_t sA = sbase + (k % 3) * W_STG;
        const uint32_t sB = sA + W_BOFF;

        #pragma unroll
        for (int ks = 0; ks < 4; ++ks) {
            const uint32_t koff = ks * 32 + lksl * 16;
            uint32_t a[MT][4];
            #pragma unroll
            for (int mt = 0; mt < MT; ++mt) {
                uint32_t ra = sA + (uint32_t)(warp_m * (16 * MT) + mt * 16 + l15) * ROWB1 + koff;
                ldsm4(a[mt][0], a[mt][1], a[mt][2], a[mt][3], ra);
            }
            uint32_t bh[2][4];
            {
                uint32_t rb = sB + (uint32_t)(warp_n * 80 + l15) * ROWB1 + koff;
                ldsm4(bh[0][0], bh[0][1], bh[0][2], bh[0][3], rb);
            }
            #pragma unroll
            for (int g = 0; g < 5; ++g) {
                const int cur = g & 1, nxt = cur ^ 1;
                if (g < 4) {
                    uint32_t rb = sB + (uint32_t)(warp_n * 80 + (g + 1) * 16 + l15) * ROWB1 + koff;
                    ldsm4(bh[nxt][0], bh[nxt][1], bh[nxt][2], bh[nxt][3], rb);
                }
                #pragma unroll
                for (int mt = 0; mt < MT; ++mt) {
                    mma_f16(acc[mt][2 * g],     a[mt], bh[cur][0], bh[cur][2]);
                    mma_f16(acc[mt][2 * g + 1], a[mt], bh[cur][1], bh[cur][3]);
                }
            }
        }
        __syncthreads();
    }

    // peeled last chunk: only ks=0 carries data (k in [6528,6544) covers CS)
    {
        CP_WAIT0();
        __syncthreads();
        const uint32_t sA = sbase + ((nk - 1) % 3) * W_STG;
        const uint32_t sB = sA + W_BOFF;
        const uint32_t koff = lksl * 16;
        uint32_t a[MT][4];
        #pragma unroll
        for (int mt = 0; mt < MT; ++mt) {
            uint32_t ra = sA + (uint32_t)(warp_m * (16 * MT) + mt * 16 + l15) * ROWB1 + koff;
            ldsm4(a[mt][0], a[mt][1], a[mt][2], a[mt][3], ra);
        }
        uint32_t bh[2][4];
        {
            uint32_t rb = sB + (uint32_t)(warp_n * 80 + l15) * ROWB1 + koff;
            ldsm4(bh[0][0], bh[0][1], bh[0][2], bh[0][3], rb);
        }
        #pragma unroll
        for (int g = 0; g < 5; ++g) {
            const int cur = g & 1, nxt = cur ^ 1;
            if (g < 4) {
                uint32_t rb = sB + (uint32_t)(warp_n * 80 + (g + 1) * 16 + l15) * ROWB1 + koff;
                ldsm4(bh[nxt][0], bh[nxt][1], bh[nxt][2], bh[nxt][3], rb);
            }
            #pragma unroll
            for (int mt = 0; mt < MT; ++mt) {
                mma_f16(acc[mt][2 * g],     a[mt], bh[cur][0], bh[cur][2]);
                mma_f16(acc[mt][2 * g + 1], a[mt], bh[cur][1], bh[cur][3]);
            }
        }
        __syncthreads();
    }

    // ---------------- fused epilogue: stage tile, reduce groups of 5 --------
    float* stg = reinterpret_cast<float*>(smem);          // [ROWS][164]
    float* v5s = stg + ROWS * W_PADN;                      // [ROWS][5]
    float* b5s = v5s + ROWS * 5;                           // [160]

    #pragma unroll
    for (int mt = 0; mt < MT; ++mt) {
        #pragma unroll
        for (int h = 0; h < 2; ++h) {
            const int row = warp_m * (16 * MT) + mt * 16 + (lane >> 2) + h * 8;
            #pragma unroll
            for (int nt = 0; nt < 10; ++nt) {
                const int col = warp_n * 80 + nt * 8 + ((lane & 3) << 1);
                stg[row * W_PADN + col]     = acc[mt][nt][h * 2 + 0];
                stg[row * W_PADN + col + 1] = acc[mt][nt][h * 2 + 1];
            }
        }
    }
    for (int i = tid; i < ROWS * 5; i += 512) v5s[i] = v5[(size_t)bm * 5 + i];
    if (tid < 160) b5s[tid] = bias5[bn + tid];
    __syncthreads();

    const int gbase = blockIdx.x * 32;
    for (int i = tid; i < ROWS * 32; i += 512) {
        const int row = i >> 5, grp = i & 31;
        const float* p  = stg + row * W_PADN + grp * 5;
        const float* vv = v5s + row * 5;
        const float* bb = b5s + grp * 5;
        float s = (p[0] + bb[0]) * vv[0];
        s = fmaf(p[1] + bb[1], vv[1], s);
        s = fmaf(p[2] + bb[2], vv[2], s);
        s = fmaf(p[3] + bb[3], vv[3], s);
        s = fmaf(p[4] + bb[4], vv[4], s);
        w[(size_t)(bm + row) * NGRP + gbase + grp] = s;
    }
}

// ---------------- transpose + fp16 (optionally compact k%6==3) --------------
__global__ __launch_bounds__(256)
void transpose_h(const float* __restrict__ W, int R, int Cstride, int nlimit,
                 __half* __restrict__ Thi, int ldt, int compact)
{
    __shared__ float ts[32][33];
    const int tx = threadIdx.x, ty = threadIdx.y;
    const int n0 = blockIdx.x * 32, k0 = blockIdx.y * 32;
    #pragma unroll
    for (int i = 0; i < 32; i += 8) {
        int k = k0 + ty + i, n = n0 + tx;
        ts[ty + i][tx] = (k < R && n < nlimit) ? W[(size_t)k * Cstride + n] : 0.f;
    }
    __syncthreads();
    #pragma unroll
    for (int i = 0; i < 32; i += 8) {
        int n = n0 + ty + i, k = k0 + tx;
        if (n < nlimit && k < R) {
            int np = n;
            if (compact) {
                int r6 = n % 6;
                if (r6 == 3) continue;
                np = (n / 6) * 5 + (r6 < 3 ? r6 : r6 - 1);
            }
            Thi[(size_t)np * ldt + k] = __float2half(ts[tx][ty + i]);
        }
    }
}

// ---------------- gather W3 tail cols + bias5 --------------------------------
__global__ __launch_bounds__(256)
void gather_tail(const float* __restrict__ W3, const float* __restrict__ b3,
                 float* __restrict__ w3t12, float* __restrict__ bias5)
{
    int i = blockIdx.x * 256 + threadIdx.x;
    if (i < CS * 12) {
        int c = i / 12, j = i % 12;
        w3t12[(size_t)j * CSP + c] = W3[(size_t)c * CS + MK + j];
    }
    if (i < MK5) {
        int m6 = i / 5, j5 = i - m6 * 5;
        int kk = (j5 < 3) ? j5 : j5 + 1;
        bias5[i] = b3[m6 * 6 + kk];
    }
}

// ---------------- z -> fp16 hi/lo (contiguous [B][128]) ---------------------
__global__ __launch_bounds__(256)
void zprep(const float* __restrict__ x, __half* __restrict__ zhi, __half* __restrict__ zlo)
{
    int i = blockIdx.x * 256 + threadIdx.x;
    if (i < B_SZ * LAT) {
        int b = i >> 7, c = i & 127;
        float v = x[(size_t)b * XCOLS + (IN_F + 1) + c];
        __half h = __float2half(v);
        zhi[i] = h;
        zlo[i] = __float2half(v - __half2float(h));
    }
}

// ---------------- tail GEMM: 32 rows/block, 8 thr/row, shfl reduce ----------
__global__ __launch_bounds__(256)
void tail_gemm(const __half* __restrict__ h2h,
               const float* __restrict__ w3t12,
               const float* __restrict__ b3,
               const float* __restrict__ x,
               float* __restrict__ v5)
{
    __shared__ __half h2s[32 * 72];
    __shared__ float  w3s[64 * 12];

    const int tid = threadIdx.x;
    const int bm = blockIdx.x * 32;
    const int row_l = tid >> 3;
    const int ksub = tid & 7;

    float acc[12];
    #pragma unroll
    for (int j = 0; j < 12; ++j) acc[j] = 0.f;

    for (int kc = 0; kc < NKCS; ++kc) {
        {
            uint4 v = *reinterpret_cast<const uint4*>(
                h2h + (size_t)(bm + row_l) * CSP + kc * 64 + ksub * 8);
            *reinterpret_cast<uint4*>(&h2s[row_l * 72 + ksub * 8]) = v;
        }
        for (int i = tid; i < 64 * 12; i += 256) {
            int k = i / 12, j = i % 12;
            w3s[i] = w3t12[(size_t)j * CSP + kc * 64 + k];
        }
        __syncthreads();

        #pragma unroll
        for (int kk = 0; kk < 8; ++kk) {
            int k = kk * 8 + ksub;
            float hv = __half2float(h2s[row_l * 72 + k]);
            #pragma unroll
            for (int j = 0; j < 12; ++j)
                acc[j] = fmaf(hv, w3s[k * 12 + j], acc[j]);
        }
        __syncthreads();
    }

    #pragma unroll
    for (int j = 0; j < 12; ++j) {
        #pragma unroll
        for (int d = 4; d > 0; d >>= 1)
            acc[j] += __shfl_down_sync(0xffffffffu, acc[j], d);
    }

    if (ksub == 0) {
        float s = x[(size_t)(B_SZ - 1) * XCOLS + IN_F];
        float dt[12];
        #pragma unroll
        for (int j = 0; j < 12; ++j) dt[j] = acc[j] + b3[MK + j];
        #pragma unroll
        for (int t5 = 0; t5 < 5; ++t5) {
            int k = (t5 < 3) ? t5 : t5 + 1;
            float sv = fmaf(s, dt[k], dt[k + 6]);
            float r = (k < 3) ? cosf(sv * (float)k) : sinf(sv * (float)(k - 3));
            v5[(size_t)(bm + row_l) * 5 + t5] = r;
        }
    }
}

// ---------------- final: out[b,o] = sum_i inp[b,i]*w[b,i*64+o] + w[b,1024+o] -
__global__ __launch_bounds__(256)
void final_kernel(const float* __restrict__ w,
                  const float* __restrict__ x,
                  float* __restrict__ out)
{
    __shared__ float inp[4][IN_F];
    const int tid = threadIdx.x;
    const int b0 = blockIdx.x * 4;
    if (tid < 4 * IN_F)
        inp[tid >> 4][tid & 15] = x[(size_t)(b0 + (tid >> 4)) * XCOLS + (tid & 15)];
    __syncthreads();

    const int r = tid >> 6;
    const int o = tid & 63;
    const int b = b0 + r;
    const float* wr = w + (size_t)b * NGRP;
    float accum = wr[1024 + o];
    #pragma unroll
    for (int i = 0; i < IN_F; ++i)
        accum = fmaf(inp[r][i], wr[i * 64 + o], accum);
    out[(size_t)b * 64 + o] = accum;
}

// ----------------------------- launch ---------------------------------------
extern "C" void kernel_launch(void* const* d_in, const int* in_sizes, int n_in,
                              void* d_out, int out_size)
{
    const float* x  = (const float*)d_in[0];
    const float* W1 = (const float*)d_in[1];
    const float* b1 = (const float*)d_in[2];
    const float* W2 = (const float*)d_in[3];
    const float* b2 = (const float*)d_in[4];
    const float* W3 = (const float*)d_in[5];
    const float* b3 = (const float*)d_in[6];
    float* out = (float*)d_out;

    __half *zhi, *zlo, *w1t, *h1h, *h2h, *w2th, *w3th;
    float *w3t12, *bias5, *wbuf, *v5;
    cudaGetSymbolAddress((void**)&zhi,  g_zhi);
    cudaGetSymbolAddress((void**)&zlo,  g_zlo);
    cudaGetSymbolAddress((void**)&w1t,  g_w1t);
    cudaGetSymbolAddress((void**)&h1h,  g_h1h);
    cudaGetSymbolAddress((void**)&h2h,  g_h2h);
    cudaGetSymbolAddress((void**)&w2th, g_w2th);
    cudaGetSymbolAddress((void**)&w3th, g_w3th);
    cudaGetSymbolAddress((void**)&w3t12, g_w3t12);
    cudaGetSymbolAddress((void**)&bias5, g_bias5);
    cudaGetSymbolAddress((void**)&wbuf, g_w);
    cudaGetSymbolAddress((void**)&v5,  g_v5);

    const int SM_2P  = 3 * 384 * ROWB1;           // 165888
    const int SM_1P  = 3 * 256 * ROWB1;           // 110592
    const int SM_W2  = 3 * (256 + 160) * ROWB1;   // 179712
    const int SM_W1  = 3 * (128 + 160) * ROWB1;   // 124416

    static bool init_done = false;
    static cudaStream_t s2;
    static cudaEvent_t evFork, evJoin;
    if (!init_done) {
        cudaFuncSetAttribute(gemm_f16<1>, cudaFuncAttributeMaxDynamicSharedMemorySize, SM_2P);
        cudaFuncSetAttribute(gemm_f16<0>, cudaFuncAttributeMaxDynamicSharedMemorySize, SM_1P);
        cudaFuncSetAttribute(gemm_w<2>, cudaFuncAttributeMaxDynamicSharedMemorySize, SM_W2);
        cudaFuncSetAttribute(gemm_w<1>, cudaFuncAttributeMaxDynamicSharedMemorySize, SM_W1);
        cudaStreamCreateWithFlags(&s2, cudaStreamNonBlocking);
        cudaEventCreateWithFlags(&evFork, cudaEventDisableTiming);
        cudaEventCreateWithFlags(&evJoin, cudaEventDisableTiming);
        init_done = true;
    }

    // 0) prep
    transpose_h<<<dim3((CS + 31) / 32, (HID + 31) / 32), dim3(32, 8)>>>(
        W2, HID, CS, CS, w2th, HID, 0);
    transpose_h<<<dim3((MK + 31) / 32, (CS + 31) / 32), dim3(32, 8)>>>(
        W3, CS, CS, MK, w3th, CSP, 1);
    transpose_h<<<dim3((HID + 31) / 32, (LAT + 31) / 32), dim3(32, 8)>>>(
        W1, LAT, HID, HID, w1t, LAT, 0);
    gather_tail<<<(CS * 12 + 255) / 256, 256>>>(W3, b3, w3t12, bias5);
    zprep<<<(B_SZ * LAT + 255) / 256, 256>>>(x, zhi, zlo);

    // 1) h1 = tanh(z @ W1 + b1): 2-pass (exact z), K=128
    gemm_f16<1><<<dim3(HID / 128, B_SZ / 128), 256, SM_2P>>>(
        zhi, zlo, LAT, w1t, LAT, LAT / 64, b1, h1h, HID, HID);

    // 2) h2 = tanh(h1 @ W2 + b2): 1-pass, K=1024
    gemm_f16<0><<<dim3(CSP / 128, B_SZ / 128), 256, SM_1P>>>(
        h1h, nullptr, HID, w2th, HID, HID / 64, b2, h2h, CSP, CS);

    // 3) tail mini-GEMM -> v5
    tail_gemm<<<B_SZ / 32, 256>>>(h2h, w3t12, b3, x, v5);

    // ---- fork: full tiles on main stream, half tiles on s2 (concurrent) ----
    cudaEventRecord(evFork, 0);
    cudaStreamWaitEvent(s2, evFork, 0);

    // 4a) rows [0, 7168): 28 full 256x160 tiles per N
    gemm_w<2><<<dim3(MK5 / 160, MFULL), 512, SM_W2>>>(
        h2h, w3th, bias5, v5, wbuf, 0);
    // 4b) rows [7168, 8192): 8 half 128x160 tiles per N (fine-grained drain)
    gemm_w<1><<<dim3(MK5 / 160, 8), 512, SM_W1, s2>>>(
        h2h, w3th, bias5, v5, wbuf, MBASE_HALF);
    cudaEventRecord(evJoin, s2);
    cudaStreamWaitEvent(0, evJoin, 0);

    // 5) adaptive 16->64 linear from fused weights
    final_kernel<<<B_SZ / 4, 256>>>(wbuf, x, out);
}